// round 11
// baseline (speedup 1.0000x reference)
#include <cuda_runtime.h>
#include <cuda_fp16.h>
#include <math.h>
#include <stdint.h>

#define Bdim 8
#define Ndim 1024
#define Ddim 1024
#define Hdim 16
#define DEPTH 64
#define MLPdim 4096
#define ROWS 8192
#define EPSLN 1e-6f
#define ISD 0.125f

__device__ float g_ao[ROWS*Ddim];
__device__ float g_attn[Bdim*Hdim*Ndim];
__device__ float g_gq[Bdim*Hdim*DEPTH];
__device__ float g_h[Bdim*Ddim];
__device__ float g_scale[Bdim*Ddim];
__device__ float g_shift[Bdim*Ddim];
__device__ __half g_xnh[ROWS*Ddim];
__device__ __half g_qh[ROWS*Ddim];
__device__ __half g_kh[ROWS*Ddim];
__device__ __half g_vh[ROWS*Ddim];
__device__ __half g_mlph[(size_t)ROWS*MLPdim];
__device__ __half g_wqh[Ddim*Ddim];
__device__ __half g_wkh[Ddim*Ddim];
__device__ __half g_wvh[Ddim*Ddim];
__device__ __half g_woh[Ddim*Ddim];
__device__ __half g_w1h[(size_t)Ddim*MLPdim];
__device__ __half g_w2h[(size_t)Ddim*MLPdim];

__device__ __forceinline__ uint32_t cvsm(const void* p){
    uint32_t a; asm("{ .reg .u64 t; cvta.to.shared.u64 t, %1; cvt.u32.u64 %0, t; }":"=r"(a):"l"(p)); return a;
}
__device__ __forceinline__ void cp16(uint32_t d, const void* s){
    asm volatile("cp.async.cg.shared.global [%0], [%1], 16;" :: "r"(d), "l"(s));
}
__device__ __forceinline__ void ldsm4(uint32_t* r, uint32_t a){
    asm volatile("ldmatrix.sync.aligned.m8n8.x4.shared.b16 {%0,%1,%2,%3},[%4];"
        : "=r"(r[0]),"=r"(r[1]),"=r"(r[2]),"=r"(r[3]) : "r"(a));
}
__device__ __forceinline__ void mma_f16(float* d, const uint32_t* a, const uint32_t* b){
    asm volatile(
        "mma.sync.aligned.m16n8k16.row.col.f32.f16.f16.f32 "
        "{%0,%1,%2,%3},{%4,%5,%6,%7},{%8,%9},{%0,%1,%2,%3};"
        : "+f"(d[0]), "+f"(d[1]), "+f"(d[2]), "+f"(d[3])
        : "r"(a[0]), "r"(a[1]), "r"(a[2]), "r"(a[3]), "r"(b[0]), "r"(b[1]));
}

// ---------------- fp16 mma GEMM: CTA 128x256, warp 64x64, 4-stage (unchanged) ----------------
#define ROWB 80
#define AB 10240
#define SLOTB 30720
#define NSTAGE 4
#define PIPESM (NSTAGE*SLOTB)

__device__ __forceinline__ void load_stage(uint32_t smb, const __half* A, const __half* Wt,
    int mBase, int nBase, int Ktot, int kB, int slot, int tid){
    uint32_t st = smb + slot*SLOTB;
    #pragma unroll
    for(int i=0;i<2;++i){
        int idx=i*256+tid, row=idx>>2, cc=idx&3;
        cp16(st + row*ROWB + cc*16, A + (size_t)(mBase+row)*Ktot + kB + cc*8);
    }
    #pragma unroll
    for(int i=0;i<4;++i){
        int idx=i*256+tid, row=idx>>2, cc=idx&3;
        cp16(st + AB + row*ROWB + cc*16, Wt + (size_t)(nBase+row)*Ktot + kB + cc*8);
    }
}

template<int EPI>
__global__ __launch_bounds__(256,1)
void hgemm(const __half* __restrict__ A, const __half* __restrict__ Wt,
           const float* __restrict__ bias, const float* __restrict__ res,
           void* __restrict__ Cv, int Ntot, int Ktot){
    extern __shared__ char smraw[];
    const uint32_t smb = cvsm(smraw);
    const int tid = threadIdx.x, lane = tid&31, warp = tid>>5;
    const int wm = warp>>2, wn = warp&3, g = lane>>2, c = lane&3;
    const int mBase = blockIdx.y*128, nBase = blockIdx.x*256;
    const int KS = Ktot/32;

    const uint32_t aoff = (uint32_t)(wm*64 + (lane&15))*ROWB + (uint32_t)(lane>>4)*16;
    const uint32_t boff = AB + (uint32_t)(wn*64 + (lane&7) + ((lane>>4)&1)*8)*ROWB
                          + (uint32_t)((lane>>3)&1)*16;

    float acc[4][8][4];
    #pragma unroll
    for(int i=0;i<4;++i)
        #pragma unroll
        for(int j=0;j<8;++j)
            #pragma unroll
            for(int q=0;q<4;++q) acc[i][j][q]=0.f;

    #pragma unroll
    for(int s=0;s<NSTAGE-1;++s){
        load_stage(smb, A, Wt, mBase, nBase, Ktot, s*32, s, tid);
        asm volatile("cp.async.commit_group;");
    }

    int slot = 0;
    for(int s=0;s<KS;++s){
        asm volatile("cp.async.wait_group %0;" :: "n"(NSTAGE-2));
        __syncthreads();
        const uint32_t sa = smb + (uint32_t)slot*SLOTB;

        uint32_t af[4][4], bf[8][2], bt[4];
        #pragma unroll
        for(int i=0;i<4;++i) ldsm4(af[i], sa + aoff + i*16*ROWB);
        #pragma unroll
        for(int jj=0;jj<4;++jj){
            ldsm4(bt, sa + boff + jj*16*ROWB);
            bf[2*jj][0]=bt[0]; bf[2*jj][1]=bt[1]; bf[2*jj+1][0]=bt[2]; bf[2*jj+1][1]=bt[3];
        }
        if(s+NSTAGE-1<KS){
            int ld = slot+NSTAGE-1; if(ld>=NSTAGE) ld-=NSTAGE;
            load_stage(smb, A, Wt, mBase, nBase, Ktot, (s+NSTAGE-1)*32, ld, tid);
        }
        asm volatile("cp.async.commit_group;");
        #pragma unroll
        for(int i=0;i<4;++i)
            #pragma unroll
            for(int j=0;j<8;++j)
                mma_f16(acc[i][j], af[i], bf[j]);

        #pragma unroll
        for(int i=0;i<4;++i) ldsm4(af[i], sa + aoff + i*16*ROWB + 32);
        #pragma unroll
        for(int jj=0;jj<4;++jj){
            ldsm4(bt, sa + boff + jj*16*ROWB + 32);
            bf[2*jj][0]=bt[0]; bf[2*jj][1]=bt[1]; bf[2*jj+1][0]=bt[2]; bf[2*jj+1][1]=bt[3];
        }
        #pragma unroll
        for(int i=0;i<4;++i)
            #pragma unroll
            for(int j=0;j<8;++j)
                mma_f16(acc[i][j], af[i], bf[j]);

        if(++slot==NSTAGE) slot=0;
    }

    #pragma unroll
    for(int i=0;i<4;++i){
        const int row0 = mBase + wm*64 + i*16 + g;
        #pragma unroll
        for(int j=0;j<8;++j){
            const int col = nBase + wn*64 + j*8 + 2*c;
            const float b0 = bias[col], b1 = bias[col+1];
            #pragma unroll
            for(int half=0;half<2;++half){
                const int row = row0 + half*8;
                float v0 = acc[i][j][half*2+0] + b0;
                float v1 = acc[i][j][half*2+1] + b1;
                const size_t off = (size_t)row*Ntot + col;
                if(EPI==1){
                    float* Cf = (float*)Cv;
                    const float2 rr = *reinterpret_cast<const float2*>(res + off);
                    float2 o; o.x = v0+rr.x; o.y = v1+rr.y;
                    *reinterpret_cast<float2*>(Cf + off) = o;
                } else {
                    if(EPI==2){
                        v0 = 0.5f*v0*(1.f+erff(v0*0.7071067811865475f));
                        v1 = 0.5f*v1*(1.f+erff(v1*0.7071067811865475f));
                    }
                    __half2* Ch = (__half2*)((__half*)Cv + off);
                    *Ch = __floats2half2_rn(v0, v1);
                }
            }
        }
    }
}

// fp32 in[K,N] -> half out[N,K]; 64x64 tiles, vectorized
__global__ __launch_bounds__(256)
void trh(const float* __restrict__ in, __half* __restrict__ out, int K, int N){
    __shared__ float t[64][65];
    const int n0 = blockIdx.x*64, k0 = blockIdx.y*64;
    const int tx = threadIdx.x & 15, ty = threadIdx.x >> 4;
    #pragma unroll
    for(int i=0;i<64;i+=16){
        float4 v = *reinterpret_cast<const float4*>(in + (size_t)(k0+ty+i)*N + n0 + tx*4);
        t[ty+i][tx*4+0]=v.x; t[ty+i][tx*4+1]=v.y; t[ty+i][tx*4+2]=v.z; t[ty+i][tx*4+3]=v.w;
    }
    __syncthreads();
    #pragma unroll
    for(int i=0;i<64;i+=16){
        const int n = ty + i, kk = tx*4;
        __half2 a = __floats2half2_rn(t[kk+0][n], t[kk+1][n]);
        __half2 b = __floats2half2_rn(t[kk+2][n], t[kk+3][n]);
        uint2 u;
        u.x = *reinterpret_cast<uint32_t*>(&a);
        u.y = *reinterpret_cast<uint32_t*>(&b);
        *reinterpret_cast<uint2*>(out + (size_t)(n0+n)*K + k0 + kk) = u;
    }
}

__device__ __forceinline__ float bsum(float v, float* sm){
    #pragma unroll
    for(int o=16;o;o>>=1) v += __shfl_xor_sync(~0u,v,o);
    int wd=threadIdx.x>>5;
    if((threadIdx.x&31)==0) sm[wd]=v;
    __syncthreads();
    float r=0.f;
    if(threadIdx.x<8){ r=sm[threadIdx.x];
        #pragma unroll
        for(int o=4;o;o>>=1) r += __shfl_xor_sync(0xFFu,r,o);
        if(threadIdx.x==0) sm[0]=r; }
    __syncthreads(); r=sm[0]; __syncthreads(); return r;
}
__device__ __forceinline__ float bmax(float v, float* sm){
    #pragma unroll
    for(int o=16;o;o>>=1) v = fmaxf(v,__shfl_xor_sync(~0u,v,o));
    int wd=threadIdx.x>>5;
    if((threadIdx.x&31)==0) sm[wd]=v;
    __syncthreads();
    float r=-1e30f;
    if(threadIdx.x<8){ r=sm[threadIdx.x];
        #pragma unroll
        for(int o=4;o;o>>=1) r = fmaxf(r,__shfl_xor_sync(0xFFu,r,o));
        if(threadIdx.x==0) sm[0]=r; }
    __syncthreads(); r=sm[0]; __syncthreads(); return r;
}

__global__ __launch_bounds__(256)
void ln_mod(const float* __restrict__ x, const float* __restrict__ sc,
            const float* __restrict__ sh, __half* __restrict__ out){
    __shared__ float sm[8];
    const int row=blockIdx.x, b=row>>10, n=row&1023;
    float4 v = reinterpret_cast<const float4*>(x+(size_t)row*Ddim)[threadIdx.x];
    float mean = bsum(v.x+v.y+v.z+v.w, sm)*(1.f/Ddim);
    float dx=v.x-mean, dy=v.y-mean, dz=v.z-mean, dw=v.w-mean;
    float var = bsum(dx*dx+dy*dy+dz*dz+dw*dw, sm)*(1.f/Ddim);
    float rs = rsqrtf(var+EPSLN);
    float s = sc[b*Ddim+n]*rs, t = sh[b*Ddim+n];
    __half2* o = reinterpret_cast<__half2*>(out+(size_t)row*Ddim) + threadIdx.x*2;
    o[0] = __floats2half2_rn(dx*s+t, dy*s+t);
    o[1] = __floats2half2_rn(dz*s+t, dw*s+t);
}

// conditioning GEMM: smem-staged activation, 8 independent accumulators
__global__ __launch_bounds__(256)
void small_gemm(const float* __restrict__ A, const float* __restrict__ W,
                const float* __restrict__ bias, float* __restrict__ out, int act){
    __shared__ float as_[Ddim];
    const int n = blockIdx.x*256+threadIdx.x, b = blockIdx.y;
    reinterpret_cast<float4*>(as_)[threadIdx.x] =
        reinterpret_cast<const float4*>(A+(size_t)b*Ddim)[threadIdx.x];
    __syncthreads();
    float acc[8];
    #pragma unroll
    for(int u=0;u<8;++u) acc[u]=0.f;
    #pragma unroll 4
    for(int k=0;k<Ddim;k+=8){
        #pragma unroll
        for(int u=0;u<8;++u)
            acc[u] = fmaf(as_[k+u], W[(size_t)(k+u)*Ddim+n], acc[u]);
    }
    float r = ((acc[0]+acc[1])+(acc[2]+acc[3])) + ((acc[4]+acc[5])+(acc[6]+acc[7]));
    r += bias[n];
    if(act) r = fmaxf(r,0.f);
    out[(size_t)b*Ddim+n]=r;
}

__global__ __launch_bounds__(256)
void qa_kernel(const __half* __restrict__ q, const float* __restrict__ w,
               const float* __restrict__ bias, float* __restrict__ attn){
    const int warp=threadIdx.x>>5, lane=threadIdx.x&31;
    const int gi=blockIdx.x*8+warp, hh=gi&15, bn=gi>>4;
    const __half2* qr = reinterpret_cast<const __half2*>(q+(size_t)bn*Ddim);
    float a0=0.f, a1=0.f;
    #pragma unroll 4
    for(int k2=lane;k2<Ddim/2;k2+=32){
        float2 x = __half22float2(qr[k2]);
        a0 = fmaf(x.x, w[(2*k2)*Hdim+hh], a0);
        a1 = fmaf(x.y, w[(2*k2+1)*Hdim+hh], a1);
    }
    float acc = a0 + a1;
    #pragma unroll
    for(int o=16;o;o>>=1) acc += __shfl_xor_sync(~0u,acc,o);
    if(lane==0){
        const int b=bn>>10, n=bn&1023;
        attn[(size_t)b*Hdim*Ndim + hh*Ndim + n] = (acc+bias[hh])*ISD;
    }
}

__global__ __launch_bounds__(256)
void softmax_kernel(float* __restrict__ attn, float* __restrict__ oa){
    __shared__ float sm[8];
    const int row=blockIdx.x;
    float4 v = reinterpret_cast<float4*>(attn+(size_t)row*Ndim)[threadIdx.x];
    float m = bmax(fmaxf(fmaxf(v.x,v.y),fmaxf(v.z,v.w)), sm);
    v.x=__expf(v.x-m); v.y=__expf(v.y-m); v.z=__expf(v.z-m); v.w=__expf(v.w-m);
    float s = bsum(v.x+v.y+v.z+v.w, sm);
    const float inv=1.f/s;
    v.x*=inv; v.y*=inv; v.z*=inv; v.w*=inv;
    reinterpret_cast<float4*>(attn+(size_t)row*Ndim)[threadIdx.x]=v;
    reinterpret_cast<float4*>(oa+(size_t)row*Ndim)[threadIdx.x]=v;
}

__global__ __launch_bounds__(256)
void globalq_kernel(const float* __restrict__ attn, const __half* __restrict__ q,
                    float* __restrict__ gq){
    __shared__ float part[256];
    const int bh=blockIdx.x, b=bh>>4, hh=bh&15;
    const int g=threadIdx.x>>6, d=threadIdx.x&63;
    const float* ar = attn+(size_t)bh*Ndim;
    float acc=0.f;
    for(int n=g;n<Ndim;n+=4)
        acc = fmaf(ar[n], __half2float(q[((size_t)(b*Ndim+n))*Ddim + hh*DEPTH + d]), acc);
    part[threadIdx.x]=acc;
    __syncthreads();
    if(g==0) gq[(size_t)bh*DEPTH+d] = part[d]+part[64+d]+part[128+d]+part[192+d];
}

// r = gq*k*v -> half (in place over v), half2 vectorized
__global__ __launch_bounds__(256)
void r_kernel(const float* __restrict__ gq, const __half2* __restrict__ k,
              __half2* __restrict__ v){
    const size_t i = (size_t)blockIdx.x*256+threadIdx.x;   // over half2 elements
    const int d2=(int)(i&511), b=(int)(i>>19);
    const float2 gg = reinterpret_cast<const float2*>(gq + b*Ddim)[d2];
    float2 kk = __half22float2(k[i]);
    float2 vv = __half22float2(v[i]);
    v[i] = __floats2half2_rn(gg.x*kk.x*vv.x, gg.y*kk.y*vv.y);
}

#define SYMF(p,s) float* p; cudaGetSymbolAddress((void**)&p, s);
#define SYMH(p,s) __half* p; cudaGetSymbolAddress((void**)&p, s);

extern "C" void kernel_launch(void* const* d_in, const int* in_sizes, int n_in,
                              void* d_out, int out_size){
    const float* inputs=(const float*)d_in[0];
    const float* z=(const float*)d_in[1];
    const float *n1_hw=(const float*)d_in[2], *n1_hb=(const float*)d_in[3];
    const float *n1_gw=(const float*)d_in[4], *n1_gb=(const float*)d_in[5];
    const float *n1_bw=(const float*)d_in[6], *n1_bb=(const float*)d_in[7];
    const float *wq_w=(const float*)d_in[8],  *wq_b=(const float*)d_in[9];
    const float *wk_w=(const float*)d_in[10], *wk_b=(const float*)d_in[11];
    const float *wv_w=(const float*)d_in[12], *wv_b=(const float*)d_in[13];
    const float *qa_w=(const float*)d_in[14], *qa_b=(const float*)d_in[15];
    const float *out_w=(const float*)d_in[16],*out_b=(const float*)d_in[17];
    const float *n2_hw=(const float*)d_in[18],*n2_hb=(const float*)d_in[19];
    const float *n2_gw=(const float*)d_in[20],*n2_gb=(const float*)d_in[21];
    const float *n2_bw=(const float*)d_in[22],*n2_bb=(const float*)d_in[23];
    const float *mw1=(const float*)d_in[24],  *mb1=(const float*)d_in[25];
    const float *mw2=(const float*)d_in[26],  *mb2=(const float*)d_in[27];

    float* out=(float*)d_out;
    float* out_attn = out + (size_t)ROWS*Ddim;

    SYMF(ao,g_ao) SYMF(attn,g_attn) SYMF(gq,g_gq) SYMF(hbuf,g_h) SYMF(sc,g_scale) SYMF(sh,g_shift)
    SYMH(xnh,g_xnh) SYMH(qh,g_qh) SYMH(kh,g_kh) SYMH(vh,g_vh) SYMH(mlph,g_mlph)
    SYMH(wqh,g_wqh) SYMH(wkh,g_wkh) SYMH(wvh,g_wvh) SYMH(woh,g_woh) SYMH(w1h,g_w1h) SYMH(w2h,g_w2h)

    cudaFuncSetAttribute(hgemm<0>, cudaFuncAttributeMaxDynamicSharedMemorySize, PIPESM);
    cudaFuncSetAttribute(hgemm<1>, cudaFuncAttributeMaxDynamicSharedMemorySize, PIPESM);
    cudaFuncSetAttribute(hgemm<2>, cudaFuncAttributeMaxDynamicSharedMemorySize, PIPESM);

    dim3 tb(256);
    trh<<<dim3(16,16),tb>>>(wq_w, wqh, Ddim, Ddim);
    trh<<<dim3(16,16),tb>>>(wk_w, wkh, Ddim, Ddim);
    trh<<<dim3(16,16),tb>>>(wv_w, wvh, Ddim, Ddim);
    trh<<<dim3(16,16),tb>>>(out_w, woh, Ddim, Ddim);
    trh<<<dim3(64,16),tb>>>(mw1, w1h, Ddim, MLPdim);
    trh<<<dim3(16,64),tb>>>(mw2, w2h, MLPdim, Ddim);

    const dim3 sg(4, Bdim);
    small_gemm<<<sg,256>>>(z, n1_hw, n1_hb, hbuf, 1);
    small_gemm<<<sg,256>>>(hbuf, n1_gw, n1_gb, sc, 0);
    small_gemm<<<sg,256>>>(hbuf, n1_bw, n1_bb, sh, 0);
    ln_mod<<<ROWS,256>>>(inputs, sc, sh, xnh);

    dim3 g1(4,64);
    hgemm<0><<<g1,256,PIPESM>>>(xnh, wqh, wq_b, nullptr, qh, Ddim, Ddim);
    hgemm<0><<<g1,256,PIPESM>>>(xnh, wkh, wk_b, nullptr, kh, Ddim, Ddim);
    hgemm<0><<<g1,256,PIPESM>>>(xnh, wvh, wv_b, nullptr, vh, Ddim, Ddim);

    qa_kernel<<<ROWS*Hdim/8,256>>>(qh, qa_w, qa_b, attn);
    softmax_kernel<<<Bdim*Hdim,256>>>(attn, out_attn);
    globalq_kernel<<<Bdim*Hdim,256>>>(attn, qh, gq);
    r_kernel<<<(size_t)ROWS*Ddim/512,256>>>(gq, (const __half2*)kh, (__half2*)vh);

    hgemm<1><<<g1,256,PIPESM>>>(vh, woh, out_b, inputs, ao, Ddim, Ddim);

    small_gemm<<<sg,256>>>(z, n2_hw, n2_hb, hbuf, 1);
    small_gemm<<<sg,256>>>(hbuf, n2_gw, n2_gb, sc, 0);
    small_gemm<<<sg,256>>>(hbuf, n2_bw, n2_bb, sh, 0);
    ln_mod<<<ROWS,256>>>(ao, sc, sh, xnh);

    dim3 g2(16,64);
    hgemm<2><<<g2,256,PIPESM>>>(xnh, w1h, mb1, nullptr, mlph, MLPdim, Ddim);
    dim3 g3(4,64);
    hgemm<1><<<g3,256,PIPESM>>>(mlph, w2h, mb2, ao, out, Ddim, MLPdim);
}

// round 12
// speedup vs baseline: 1.1967x; 1.1967x over previous
#include <cuda_runtime.h>
#include <cuda_fp16.h>
#include <math.h>
#include <stdint.h>

#define Bdim 8
#define Ndim 1024
#define Ddim 1024
#define Hdim 16
#define DEPTH 64
#define MLPdim 4096
#define ROWS 8192
#define EPSLN 1e-6f
#define ISD 0.125f

__device__ float g_ao[ROWS*Ddim];
__device__ float g_attn[Bdim*Hdim*Ndim];
__device__ float g_gq[Bdim*Hdim*DEPTH];
__device__ float g_h[Bdim*Ddim];
__device__ float g_scale[Bdim*Ddim];
__device__ float g_shift[Bdim*Ddim];
__device__ float g_qkvb[3*Ddim];
__device__ __half g_xnh[ROWS*Ddim];
__device__ __half g_qh[ROWS*Ddim];
__device__ __half g_kh[ROWS*Ddim];
__device__ __half g_vh[ROWS*Ddim];
__device__ __half g_mlph[(size_t)ROWS*MLPdim];
__device__ __half g_wqkv[(size_t)3*Ddim*Ddim];
__device__ __half g_woh[Ddim*Ddim];
__device__ __half g_w1h[(size_t)Ddim*MLPdim];
__device__ __half g_w2h[(size_t)Ddim*MLPdim];

__device__ __forceinline__ uint32_t cvsm(const void* p){
    uint32_t a; asm("{ .reg .u64 t; cvta.to.shared.u64 t, %1; cvt.u32.u64 %0, t; }":"=r"(a):"l"(p)); return a;
}
__device__ __forceinline__ void cp16(uint32_t d, const void* s){
    asm volatile("cp.async.cg.shared.global [%0], [%1], 16;" :: "r"(d), "l"(s));
}
__device__ __forceinline__ void ldsm4(uint32_t* r, uint32_t a){
    asm volatile("ldmatrix.sync.aligned.m8n8.x4.shared.b16 {%0,%1,%2,%3},[%4];"
        : "=r"(r[0]),"=r"(r[1]),"=r"(r[2]),"=r"(r[3]) : "r"(a));
}
__device__ __forceinline__ void mma_f16(float* d, const uint32_t* a, const uint32_t* b){
    asm volatile(
        "mma.sync.aligned.m16n8k16.row.col.f32.f16.f16.f32 "
        "{%0,%1,%2,%3},{%4,%5,%6,%7},{%8,%9},{%0,%1,%2,%3};"
        : "+f"(d[0]), "+f"(d[1]), "+f"(d[2]), "+f"(d[3])
        : "r"(a[0]), "r"(a[1]), "r"(a[2]), "r"(a[3]), "r"(b[0]), "r"(b[1]));
}

// ---------------- fp16 mma GEMM: CTA 128x256, warp 64x64, 4-stage ----------------
// EPI: 0 half(+b) ; 1 f32 +b+res ; 2 half gelu(+b) ; 3 QKV split (C0/C1/C2, bias 3072)
#define ROWB 80
#define AB 10240
#define SLOTB 30720
#define NSTAGE 4
#define PIPESM (NSTAGE*SLOTB)

__device__ __forceinline__ void load_stage(uint32_t smb, const __half* A, const __half* Wt,
    int mBase, int nBase, int Ktot, int kB, int slot, int tid){
    uint32_t st = smb + slot*SLOTB;
    #pragma unroll
    for(int i=0;i<2;++i){
        int idx=i*256+tid, row=idx>>2, cc=idx&3;
        cp16(st + row*ROWB + cc*16, A + (size_t)(mBase+row)*Ktot + kB + cc*8);
    }
    #pragma unroll
    for(int i=0;i<4;++i){
        int idx=i*256+tid, row=idx>>2, cc=idx&3;
        cp16(st + AB + row*ROWB + cc*16, Wt + (size_t)(nBase+row)*Ktot + kB + cc*8);
    }
}

template<int EPI>
__global__ __launch_bounds__(256,1)
void hgemm(const __half* __restrict__ A, const __half* __restrict__ Wt,
           const float* __restrict__ bias, const float* __restrict__ res,
           void* __restrict__ Cv, void* __restrict__ C1, void* __restrict__ C2,
           int Ntot, int Ktot){
    extern __shared__ char smraw[];
    const uint32_t smb = cvsm(smraw);
    const int tid = threadIdx.x, lane = tid&31, warp = tid>>5;
    const int wm = warp>>2, wn = warp&3, g = lane>>2, c = lane&3;
    const int mBase = blockIdx.y*128, nBase = blockIdx.x*256;
    const int KS = Ktot/32;

    const uint32_t aoff = (uint32_t)(wm*64 + (lane&15))*ROWB + (uint32_t)(lane>>4)*16;
    const uint32_t boff = AB + (uint32_t)(wn*64 + (lane&7) + ((lane>>4)&1)*8)*ROWB
                          + (uint32_t)((lane>>3)&1)*16;

    float acc[4][8][4];
    #pragma unroll
    for(int i=0;i<4;++i)
        #pragma unroll
        for(int j=0;j<8;++j)
            #pragma unroll
            for(int q=0;q<4;++q) acc[i][j][q]=0.f;

    #pragma unroll
    for(int s=0;s<NSTAGE-1;++s){
        load_stage(smb, A, Wt, mBase, nBase, Ktot, s*32, s, tid);
        asm volatile("cp.async.commit_group;");
    }

    int slot = 0;
    for(int s=0;s<KS;++s){
        asm volatile("cp.async.wait_group %0;" :: "n"(NSTAGE-2));
        __syncthreads();
        const uint32_t sa = smb + (uint32_t)slot*SLOTB;

        uint32_t af[4][4], bf[8][2], bt[4];
        #pragma unroll
        for(int i=0;i<4;++i) ldsm4(af[i], sa + aoff + i*16*ROWB);
        #pragma unroll
        for(int jj=0;jj<4;++jj){
            ldsm4(bt, sa + boff + jj*16*ROWB);
            bf[2*jj][0]=bt[0]; bf[2*jj][1]=bt[1]; bf[2*jj+1][0]=bt[2]; bf[2*jj+1][1]=bt[3];
        }
        if(s+NSTAGE-1<KS){
            int ld = slot+NSTAGE-1; if(ld>=NSTAGE) ld-=NSTAGE;
            load_stage(smb, A, Wt, mBase, nBase, Ktot, (s+NSTAGE-1)*32, ld, tid);
        }
        asm volatile("cp.async.commit_group;");
        #pragma unroll
        for(int i=0;i<4;++i)
            #pragma unroll
            for(int j=0;j<8;++j)
                mma_f16(acc[i][j], af[i], bf[j]);

        #pragma unroll
        for(int i=0;i<4;++i) ldsm4(af[i], sa + aoff + i*16*ROWB + 32);
        #pragma unroll
        for(int jj=0;jj<4;++jj){
            ldsm4(bt, sa + boff + jj*16*ROWB + 32);
            bf[2*jj][0]=bt[0]; bf[2*jj][1]=bt[1]; bf[2*jj+1][0]=bt[2]; bf[2*jj+1][1]=bt[3];
        }
        #pragma unroll
        for(int i=0;i<4;++i)
            #pragma unroll
            for(int j=0;j<8;++j)
                mma_f16(acc[i][j], af[i], bf[j]);

        if(++slot==NSTAGE) slot=0;
    }

    // output base for EPI==3 (CTA-uniform: nBase multiple of 256, 1024/256=4)
    __half* Cq = (__half*)Cv;
    if(EPI==3){
        const int sel = nBase>>10;
        Cq = sel==0 ? (__half*)Cv : (sel==1 ? (__half*)C1 : (__half*)C2);
    }

    #pragma unroll
    for(int i=0;i<4;++i){
        const int row0 = mBase + wm*64 + i*16 + g;
        #pragma unroll
        for(int j=0;j<8;++j){
            const int colg = nBase + wn*64 + j*8 + 2*c;
            const float b0 = bias[colg], b1 = bias[colg+1];
            #pragma unroll
            for(int half=0;half<2;++half){
                const int row = row0 + half*8;
                float v0 = acc[i][j][half*2+0] + b0;
                float v1 = acc[i][j][half*2+1] + b1;
                if(EPI==1){
                    const size_t off = (size_t)row*Ntot + colg;
                    float* Cf = (float*)Cv;
                    const float2 rr = *reinterpret_cast<const float2*>(res + off);
                    float2 o; o.x = v0+rr.x; o.y = v1+rr.y;
                    *reinterpret_cast<float2*>(Cf + off) = o;
                } else if(EPI==3){
                    const size_t off = (size_t)row*Ddim + (colg&1023);
                    *(__half2*)(Cq + off) = __floats2half2_rn(v0, v1);
                } else {
                    if(EPI==2){
                        v0 = 0.5f*v0*(1.f+erff(v0*0.7071067811865475f));
                        v1 = 0.5f*v1*(1.f+erff(v1*0.7071067811865475f));
                    }
                    const size_t off = (size_t)row*Ntot + colg;
                    *(__half2*)((__half*)Cv + off) = __floats2half2_rn(v0, v1);
                }
            }
        }
    }
}

// fp32 in[K,N] -> half out[N,K]
__global__ __launch_bounds__(256)
void trh(const float* __restrict__ in, __half* __restrict__ out, int K, int N){
    __shared__ float t[32][33];
    const int n0 = blockIdx.x*32, k0 = blockIdx.y*32;
    const int tx = threadIdx.x & 31, ty = threadIdx.x >> 5;
    #pragma unroll
    for(int i=0;i<32;i+=8)
        t[ty+i][tx] = in[(size_t)(k0+ty+i)*N + n0+tx];
    __syncthreads();
    #pragma unroll
    for(int i=0;i<32;i+=8)
        out[(size_t)(n0+ty+i)*K + k0+tx] = __float2half_rn(t[tx][ty+i]);
}

__global__ void concat3(const float* __restrict__ a, const float* __restrict__ b,
                        const float* __restrict__ c, float* __restrict__ o){
    const int i = blockIdx.x*256+threadIdx.x;
    o[i] = (i<1024) ? a[i] : ((i<2048) ? b[i-1024] : c[i-2048]);
}

__device__ __forceinline__ float bsum(float v, float* sm){
    #pragma unroll
    for(int o=16;o;o>>=1) v += __shfl_xor_sync(~0u,v,o);
    int wd=threadIdx.x>>5;
    if((threadIdx.x&31)==0) sm[wd]=v;
    __syncthreads();
    float r=0.f;
    if(threadIdx.x<8){ r=sm[threadIdx.x];
        #pragma unroll
        for(int o=4;o;o>>=1) r += __shfl_xor_sync(0xFFu,r,o);
        if(threadIdx.x==0) sm[0]=r; }
    __syncthreads(); r=sm[0]; __syncthreads(); return r;
}
__device__ __forceinline__ float bmax(float v, float* sm){
    #pragma unroll
    for(int o=16;o;o>>=1) v = fmaxf(v,__shfl_xor_sync(~0u,v,o));
    int wd=threadIdx.x>>5;
    if((threadIdx.x&31)==0) sm[wd]=v;
    __syncthreads();
    float r=-1e30f;
    if(threadIdx.x<8){ r=sm[threadIdx.x];
        #pragma unroll
        for(int o=4;o;o>>=1) r = fmaxf(r,__shfl_xor_sync(0xFFu,r,o));
        if(threadIdx.x==0) sm[0]=r; }
    __syncthreads(); r=sm[0]; __syncthreads(); return r;
}

__global__ __launch_bounds__(256)
void ln_mod(const float* __restrict__ x, const float* __restrict__ sc,
            const float* __restrict__ sh, __half* __restrict__ out){
    __shared__ float sm[8];
    const int row=blockIdx.x, b=row>>10, n=row&1023;
    float4 v = reinterpret_cast<const float4*>(x+(size_t)row*Ddim)[threadIdx.x];
    float mean = bsum(v.x+v.y+v.z+v.w, sm)*(1.f/Ddim);
    float dx=v.x-mean, dy=v.y-mean, dz=v.z-mean, dw=v.w-mean;
    float var = bsum(dx*dx+dy*dy+dz*dz+dw*dw, sm)*(1.f/Ddim);
    float rs = rsqrtf(var+EPSLN);
    float s = sc[b*Ddim+n]*rs, t = sh[b*Ddim+n];
    __half2* o = reinterpret_cast<__half2*>(out+(size_t)row*Ddim) + threadIdx.x*2;
    o[0] = __floats2half2_rn(dx*s+t, dy*s+t);
    o[1] = __floats2half2_rn(dz*s+t, dw*s+t);
}

// h = relu(z@W+b)
__global__ __launch_bounds__(256)
void small_gemm(const float* __restrict__ A, const float* __restrict__ W,
                const float* __restrict__ bias, float* __restrict__ out, int act){
    const int n = blockIdx.x*256+threadIdx.x, b = blockIdx.y;
    const float* a = A+(size_t)b*Ddim;
    float acc=0.f;
    for(int k=0;k<Ddim;++k) acc = fmaf(a[k], W[(size_t)k*Ddim+n], acc);
    acc += bias[n];
    if(act) acc = fmaxf(acc,0.f);
    out[(size_t)b*Ddim+n]=acc;
}

// two independent conditioning GEMMs in one launch (blockIdx.z selects)
__global__ __launch_bounds__(256)
void cond2(const float* __restrict__ hb,
           const float* __restrict__ W0, const float* __restrict__ b0, float* __restrict__ o0,
           const float* __restrict__ W1, const float* __restrict__ b1, float* __restrict__ o1){
    const float* W = blockIdx.z ? W1 : W0;
    const float* bi = blockIdx.z ? b1 : b0;
    float* o = blockIdx.z ? o1 : o0;
    const int n = blockIdx.x*256+threadIdx.x, b = blockIdx.y;
    const float* a = hb+(size_t)b*Ddim;
    float acc=0.f;
    for(int k=0;k<Ddim;++k) acc = fmaf(a[k], W[(size_t)k*Ddim+n], acc);
    o[(size_t)b*Ddim+n] = acc + bi[n];
}

__global__ __launch_bounds__(256)
void qa_kernel(const __half* __restrict__ q, const float* __restrict__ w,
               const float* __restrict__ bias, float* __restrict__ attn){
    const int warp=threadIdx.x>>5, lane=threadIdx.x&31;
    const int gi=blockIdx.x*8+warp, hh=gi&15, bn=gi>>4;
    const __half* qr = q+(size_t)bn*Ddim;
    float acc=0.f;
    #pragma unroll 4
    for(int k=lane;k<Ddim;k+=32) acc = fmaf(__half2float(qr[k]), w[k*Hdim+hh], acc);
    #pragma unroll
    for(int o=16;o;o>>=1) acc += __shfl_xor_sync(~0u,acc,o);
    if(lane==0){
        const int b=bn>>10, n=bn&1023;
        attn[(size_t)b*Hdim*Ndim + hh*Ndim + n] = (acc+bias[hh])*ISD;
    }
}

__global__ __launch_bounds__(256)
void softmax_kernel(float* __restrict__ attn, float* __restrict__ oa){
    __shared__ float sm[8];
    const int row=blockIdx.x;
    float4 v = reinterpret_cast<float4*>(attn+(size_t)row*Ndim)[threadIdx.x];
    float m = bmax(fmaxf(fmaxf(v.x,v.y),fmaxf(v.z,v.w)), sm);
    v.x=__expf(v.x-m); v.y=__expf(v.y-m); v.z=__expf(v.z-m); v.w=__expf(v.w-m);
    float s = bsum(v.x+v.y+v.z+v.w, sm);
    const float inv=1.f/s;
    v.x*=inv; v.y*=inv; v.z*=inv; v.w*=inv;
    reinterpret_cast<float4*>(attn+(size_t)row*Ndim)[threadIdx.x]=v;
    reinterpret_cast<float4*>(oa+(size_t)row*Ndim)[threadIdx.x]=v;
}

__global__ __launch_bounds__(256)
void globalq_kernel(const float* __restrict__ attn, const __half* __restrict__ q,
                    float* __restrict__ gq){
    __shared__ float part[256];
    const int bh=blockIdx.x, b=bh>>4, hh=bh&15;
    const int g=threadIdx.x>>6, d=threadIdx.x&63;
    const float* ar = attn+(size_t)bh*Ndim;
    float acc=0.f;
    for(int n=g;n<Ndim;n+=4)
        acc = fmaf(ar[n], __half2float(q[((size_t)(b*Ndim+n))*Ddim + hh*DEPTH + d]), acc);
    part[threadIdx.x]=acc;
    __syncthreads();
    if(g==0) gq[(size_t)bh*DEPTH+d] = part[d]+part[64+d]+part[128+d]+part[192+d];
}

__global__ __launch_bounds__(256)
void r_kernel(const float* __restrict__ gq, const __half* __restrict__ k,
              __half* __restrict__ v){
    const size_t i = (size_t)blockIdx.x*256+threadIdx.x;
    const int d=(int)(i&1023), b=(int)(i>>20);
    v[i] = __float2half_rn(gq[b*Ddim+d]*__half2float(k[i])*__half2float(v[i]));
}

#define SYMF(p,s) float* p; cudaGetSymbolAddress((void**)&p, s);
#define SYMH(p,s) __half* p; cudaGetSymbolAddress((void**)&p, s);

extern "C" void kernel_launch(void* const* d_in, const int* in_sizes, int n_in,
                              void* d_out, int out_size){
    const float* inputs=(const float*)d_in[0];
    const float* z=(const float*)d_in[1];
    const float *n1_hw=(const float*)d_in[2], *n1_hb=(const float*)d_in[3];
    const float *n1_gw=(const float*)d_in[4], *n1_gb=(const float*)d_in[5];
    const float *n1_bw=(const float*)d_in[6], *n1_bb=(const float*)d_in[7];
    const float *wq_w=(const float*)d_in[8],  *wq_b=(const float*)d_in[9];
    const float *wk_w=(const float*)d_in[10], *wk_b=(const float*)d_in[11];
    const float *wv_w=(const float*)d_in[12], *wv_b=(const float*)d_in[13];
    const float *qa_w=(const float*)d_in[14], *qa_b=(const float*)d_in[15];
    const float *out_w=(const float*)d_in[16],*out_b=(const float*)d_in[17];
    const float *n2_hw=(const float*)d_in[18],*n2_hb=(const float*)d_in[19];
    const float *n2_gw=(const float*)d_in[20],*n2_gb=(const float*)d_in[21];
    const float *n2_bw=(const float*)d_in[22],*n2_bb=(const float*)d_in[23];
    const float *mw1=(const float*)d_in[24],  *mb1=(const float*)d_in[25];
    const float *mw2=(const float*)d_in[26],  *mb2=(const float*)d_in[27];

    float* out=(float*)d_out;
    float* out_attn = out + (size_t)ROWS*Ddim;

    SYMF(ao,g_ao) SYMF(attn,g_attn) SYMF(gq,g_gq) SYMF(hbuf,g_h) SYMF(sc,g_scale) SYMF(sh,g_shift)
    SYMF(qkvb,g_qkvb)
    SYMH(xnh,g_xnh) SYMH(qh,g_qh) SYMH(kh,g_kh) SYMH(vh,g_vh) SYMH(mlph,g_mlph)
    SYMH(wqkv,g_wqkv) SYMH(woh,g_woh) SYMH(w1h,g_w1h) SYMH(w2h,g_w2h)

    cudaFuncSetAttribute(hgemm<1>, cudaFuncAttributeMaxDynamicSharedMemorySize, PIPESM);
    cudaFuncSetAttribute(hgemm<2>, cudaFuncAttributeMaxDynamicSharedMemorySize, PIPESM);
    cudaFuncSetAttribute(hgemm<3>, cudaFuncAttributeMaxDynamicSharedMemorySize, PIPESM);

    dim3 tb(32,8);
    trh<<<dim3(32,32),256>>>(wq_w, wqkv, Ddim, Ddim);
    trh<<<dim3(32,32),256>>>(wk_w, wqkv + (size_t)Ddim*Ddim, Ddim, Ddim);
    trh<<<dim3(32,32),256>>>(wv_w, wqkv + (size_t)2*Ddim*Ddim, Ddim, Ddim);
    trh<<<dim3(32,32),256>>>(out_w, woh, Ddim, Ddim);
    trh<<<dim3(128,32),256>>>(mw1, w1h, Ddim, MLPdim);
    trh<<<dim3(32,128),256>>>(mw2, w2h, MLPdim, Ddim);
    concat3<<<12,256>>>(wq_b, wk_b, wv_b, qkvb);

    const dim3 sg(4, Bdim);
    small_gemm<<<sg,256>>>(z, n1_hw, n1_hb, hbuf, 1);
    cond2<<<dim3(4,Bdim,2),256>>>(hbuf, n1_gw, n1_gb, sc, n1_bw, n1_bb, sh);
    ln_mod<<<ROWS,256>>>(inputs, sc, sh, xnh);

    // fused QKV
    hgemm<3><<<dim3(12,64),256,PIPESM>>>(xnh, wqkv, qkvb, nullptr, qh, kh, vh, Ddim, Ddim);

    qa_kernel<<<ROWS*Hdim/8,256>>>(qh, qa_w, qa_b, attn);
    softmax_kernel<<<Bdim*Hdim,256>>>(attn, out_attn);
    globalq_kernel<<<Bdim*Hdim,256>>>(attn, qh, gq);
    r_kernel<<<(size_t)ROWS*Ddim/256,256>>>(gq, kh, vh);

    hgemm<1><<<dim3(4,64),256,PIPESM>>>(vh, woh, out_b, inputs, ao, nullptr, nullptr, Ddim, Ddim);

    small_gemm<<<sg,256>>>(z, n2_hw, n2_hb, hbuf, 1);
    cond2<<<dim3(4,Bdim,2),256>>>(hbuf, n2_gw, n2_gb, sc, n2_bw, n2_bb, sh);
    ln_mod<<<ROWS,256>>>(ao, sc, sh, xnh);

    hgemm<2><<<dim3(16,64),256,PIPESM>>>(xnh, w1h, mb1, nullptr, mlph, nullptr, nullptr, MLPdim, Ddim);
    hgemm<1><<<dim3(4,64),256,PIPESM>>>(mlph, w2h, mb2, ao, out, nullptr, nullptr, Ddim, MLPdim);
}

// round 13
// speedup vs baseline: 1.3484x; 1.1267x over previous
#include <cuda_runtime.h>
#include <cuda_fp16.h>
#include <math.h>
#include <stdint.h>

#define Bdim 8
#define Ndim 1024
#define Ddim 1024
#define Hdim 16
#define DEPTH 64
#define MLPdim 4096
#define ROWS 8192
#define EPSLN 1e-6f
#define ISD 0.125f

__device__ float g_ao[ROWS*Ddim];
__device__ float g_attn[Bdim*Hdim*Ndim];
__device__ float g_gq[Bdim*Hdim*DEPTH];
__device__ float g_h[Bdim*Ddim];
__device__ float g_h2[Bdim*Ddim];
__device__ float g_scale[Bdim*Ddim];
__device__ float g_shift[Bdim*Ddim];
__device__ float g_scale2[Bdim*Ddim];
__device__ float g_shift2[Bdim*Ddim];
__device__ float g_qkvb[3*Ddim];
__device__ __half g_xnh[ROWS*Ddim];
__device__ __half g_qh[ROWS*Ddim];
__device__ __half g_kh[ROWS*Ddim];
__device__ __half g_vh[ROWS*Ddim];
__device__ __half g_mlph[(size_t)ROWS*MLPdim];
__device__ __half g_wqkv[(size_t)3*Ddim*Ddim];
__device__ __half g_woh[Ddim*Ddim];
__device__ __half g_w1h[(size_t)Ddim*MLPdim];
__device__ __half g_w2h[(size_t)Ddim*MLPdim];

__device__ __forceinline__ uint32_t cvsm(const void* p){
    uint32_t a; asm("{ .reg .u64 t; cvta.to.shared.u64 t, %1; cvt.u32.u64 %0, t; }":"=r"(a):"l"(p)); return a;
}
__device__ __forceinline__ void cp16(uint32_t d, const void* s){
    asm volatile("cp.async.cg.shared.global [%0], [%1], 16;" :: "r"(d), "l"(s));
}
__device__ __forceinline__ void ldsm4(uint32_t* r, uint32_t a){
    asm volatile("ldmatrix.sync.aligned.m8n8.x4.shared.b16 {%0,%1,%2,%3},[%4];"
        : "=r"(r[0]),"=r"(r[1]),"=r"(r[2]),"=r"(r[3]) : "r"(a));
}
__device__ __forceinline__ void mma_f16(float* d, const uint32_t* a, const uint32_t* b){
    asm volatile(
        "mma.sync.aligned.m16n8k16.row.col.f32.f16.f16.f32 "
        "{%0,%1,%2,%3},{%4,%5,%6,%7},{%8,%9},{%0,%1,%2,%3};"
        : "+f"(d[0]), "+f"(d[1]), "+f"(d[2]), "+f"(d[3])
        : "r"(a[0]), "r"(a[1]), "r"(a[2]), "r"(a[3]), "r"(b[0]), "r"(b[1]));
}

// ---------------- fp16 mma GEMM: CTA 128x256, warp 64x64, 4-stage ----------------
#define ROWB 80
#define AB 10240
#define SLOTB 30720
#define NSTAGE 4
#define PIPESM (NSTAGE*SLOTB)

__device__ __forceinline__ void load_stage(uint32_t smb, const __half* A, const __half* Wt,
    int mBase, int nBase, int Ktot, int kB, int slot, int tid){
    uint32_t st = smb + slot*SLOTB;
    #pragma unroll
    for(int i=0;i<2;++i){
        int idx=i*256+tid, row=idx>>2, cc=idx&3;
        cp16(st + row*ROWB + cc*16, A + (size_t)(mBase+row)*Ktot + kB + cc*8);
    }
    #pragma unroll
    for(int i=0;i<4;++i){
        int idx=i*256+tid, row=idx>>2, cc=idx&3;
        cp16(st + AB + row*ROWB + cc*16, Wt + (size_t)(nBase+row)*Ktot + kB + cc*8);
    }
}

template<int EPI>
__global__ __launch_bounds__(256,1)
void hgemm(const __half* __restrict__ A, const __half* __restrict__ Wt,
           const float* __restrict__ bias, const float* __restrict__ res,
           void* __restrict__ Cv, void* __restrict__ C1, void* __restrict__ C2,
           int Ntot, int Ktot){
    extern __shared__ char smraw[];
    const uint32_t smb = cvsm(smraw);
    const int tid = threadIdx.x, lane = tid&31, warp = tid>>5;
    const int wm = warp>>2, wn = warp&3, g = lane>>2, c = lane&3;
    const int mBase = blockIdx.y*128, nBase = blockIdx.x*256;
    const int KS = Ktot/32;

    const uint32_t aoff = (uint32_t)(wm*64 + (lane&15))*ROWB + (uint32_t)(lane>>4)*16;
    const uint32_t boff = AB + (uint32_t)(wn*64 + (lane&7) + ((lane>>4)&1)*8)*ROWB
                          + (uint32_t)((lane>>3)&1)*16;

    float acc[4][8][4];
    #pragma unroll
    for(int i=0;i<4;++i)
        #pragma unroll
        for(int j=0;j<8;++j)
            #pragma unroll
            for(int q=0;q<4;++q) acc[i][j][q]=0.f;

    #pragma unroll
    for(int s=0;s<NSTAGE-1;++s){
        load_stage(smb, A, Wt, mBase, nBase, Ktot, s*32, s, tid);
        asm volatile("cp.async.commit_group;");
    }

    int slot = 0;
    for(int s=0;s<KS;++s){
        asm volatile("cp.async.wait_group %0;" :: "n"(NSTAGE-2));
        __syncthreads();
        const uint32_t sa = smb + (uint32_t)slot*SLOTB;

        uint32_t af[4][4], bf[8][2], bt[4];
        #pragma unroll
        for(int i=0;i<4;++i) ldsm4(af[i], sa + aoff + i*16*ROWB);
        #pragma unroll
        for(int jj=0;jj<4;++jj){
            ldsm4(bt, sa + boff + jj*16*ROWB);
            bf[2*jj][0]=bt[0]; bf[2*jj][1]=bt[1]; bf[2*jj+1][0]=bt[2]; bf[2*jj+1][1]=bt[3];
        }
        if(s+NSTAGE-1<KS){
            int ld = slot+NSTAGE-1; if(ld>=NSTAGE) ld-=NSTAGE;
            load_stage(smb, A, Wt, mBase, nBase, Ktot, (s+NSTAGE-1)*32, ld, tid);
        }
        asm volatile("cp.async.commit_group;");
        #pragma unroll
        for(int i=0;i<4;++i)
            #pragma unroll
            for(int j=0;j<8;++j)
                mma_f16(acc[i][j], af[i], bf[j]);

        #pragma unroll
        for(int i=0;i<4;++i) ldsm4(af[i], sa + aoff + i*16*ROWB + 32);
        #pragma unroll
        for(int jj=0;jj<4;++jj){
            ldsm4(bt, sa + boff + jj*16*ROWB + 32);
            bf[2*jj][0]=bt[0]; bf[2*jj][1]=bt[1]; bf[2*jj+1][0]=bt[2]; bf[2*jj+1][1]=bt[3];
        }
        #pragma unroll
        for(int i=0;i<4;++i)
            #pragma unroll
            for(int j=0;j<8;++j)
                mma_f16(acc[i][j], af[i], bf[j]);

        if(++slot==NSTAGE) slot=0;
    }

    __half* Cq = (__half*)Cv;
    if(EPI==3){
        const int sel = nBase>>10;
        Cq = sel==0 ? (__half*)Cv : (sel==1 ? (__half*)C1 : (__half*)C2);
    }

    #pragma unroll
    for(int i=0;i<4;++i){
        const int row0 = mBase + wm*64 + i*16 + g;
        #pragma unroll
        for(int j=0;j<8;++j){
            const int colg = nBase + wn*64 + j*8 + 2*c;
            const float b0 = bias[colg], b1 = bias[colg+1];
            #pragma unroll
            for(int half=0;half<2;++half){
                const int row = row0 + half*8;
                float v0 = acc[i][j][half*2+0] + b0;
                float v1 = acc[i][j][half*2+1] + b1;
                if(EPI==1){
                    const size_t off = (size_t)row*Ntot + colg;
                    float* Cf = (float*)Cv;
                    const float2 rr = *reinterpret_cast<const float2*>(res + off);
                    float2 o; o.x = v0+rr.x; o.y = v1+rr.y;
                    *reinterpret_cast<float2*>(Cf + off) = o;
                } else if(EPI==3){
                    const size_t off = (size_t)row*Ddim + (colg&1023);
                    *(__half2*)(Cq + off) = __floats2half2_rn(v0, v1);
                } else {
                    if(EPI==2){
                        v0 = 0.5f*v0*(1.f+erff(v0*0.7071067811865475f));
                        v1 = 0.5f*v1*(1.f+erff(v1*0.7071067811865475f));
                    }
                    const size_t off = (size_t)row*Ntot + colg;
                    *(__half2*)((__half*)Cv + off) = __floats2half2_rn(v0, v1);
                }
            }
        }
    }
}

__global__ __launch_bounds__(256)
void trh(const float* __restrict__ in, __half* __restrict__ out, int K, int N){
    __shared__ float t[32][33];
    const int n0 = blockIdx.x*32, k0 = blockIdx.y*32;
    const int tx = threadIdx.x & 31, ty = threadIdx.x >> 5;
    #pragma unroll
    for(int i=0;i<32;i+=8)
        t[ty+i][tx] = in[(size_t)(k0+ty+i)*N + n0+tx];
    __syncthreads();
    #pragma unroll
    for(int i=0;i<32;i+=8)
        out[(size_t)(n0+ty+i)*K + k0+tx] = __float2half_rn(t[tx][ty+i]);
}

__global__ void concat3(const float* __restrict__ a, const float* __restrict__ b,
                        const float* __restrict__ c, float* __restrict__ o){
    const int i = blockIdx.x*256+threadIdx.x;
    o[i] = (i<1024) ? a[i] : ((i<2048) ? b[i-1024] : c[i-2048]);
}

__device__ __forceinline__ float bsum(float v, float* sm){
    #pragma unroll
    for(int o=16;o;o>>=1) v += __shfl_xor_sync(~0u,v,o);
    int wd=threadIdx.x>>5;
    if((threadIdx.x&31)==0) sm[wd]=v;
    __syncthreads();
    float r=0.f;
    if(threadIdx.x<8){ r=sm[threadIdx.x];
        #pragma unroll
        for(int o=4;o;o>>=1) r += __shfl_xor_sync(0xFFu,r,o);
        if(threadIdx.x==0) sm[0]=r; }
    __syncthreads(); r=sm[0]; __syncthreads(); return r;
}
__device__ __forceinline__ float bmax(float v, float* sm){
    #pragma unroll
    for(int o=16;o;o>>=1) v = fmaxf(v,__shfl_xor_sync(~0u,v,o));
    int wd=threadIdx.x>>5;
    if((threadIdx.x&31)==0) sm[wd]=v;
    __syncthreads();
    float r=-1e30f;
    if(threadIdx.x<8){ r=sm[threadIdx.x];
        #pragma unroll
        for(int o=4;o;o>>=1) r = fmaxf(r,__shfl_xor_sync(0xFFu,r,o));
        if(threadIdx.x==0) sm[0]=r; }
    __syncthreads(); r=sm[0]; __syncthreads(); return r;
}

__global__ __launch_bounds__(256)
void ln_mod(const float* __restrict__ x, const float* __restrict__ sc,
            const float* __restrict__ sh, __half* __restrict__ out){
    __shared__ float sm[8];
    const int row=blockIdx.x, b=row>>10, n=row&1023;
    float4 v = reinterpret_cast<const float4*>(x+(size_t)row*Ddim)[threadIdx.x];
    float mean = bsum(v.x+v.y+v.z+v.w, sm)*(1.f/Ddim);
    float dx=v.x-mean, dy=v.y-mean, dz=v.z-mean, dw=v.w-mean;
    float var = bsum(dx*dx+dy*dy+dz*dz+dw*dw, sm)*(1.f/Ddim);
    float rs = rsqrtf(var+EPSLN);
    float s = sc[b*Ddim+n]*rs, t = sh[b*Ddim+n];
    __half2* o = reinterpret_cast<__half2*>(out+(size_t)row*Ddim) + threadIdx.x*2;
    o[0] = __floats2half2_rn(dx*s+t, dy*s+t);
    o[1] = __floats2half2_rn(dz*s+t, dw*s+t);
}

__global__ __launch_bounds__(256)
void small_gemm(const float* __restrict__ A, const float* __restrict__ W,
                const float* __restrict__ bias, float* __restrict__ out, int act){
    const int n = blockIdx.x*256+threadIdx.x, b = blockIdx.y;
    const float* a = A+(size_t)b*Ddim;
    float acc=0.f;
    for(int k=0;k<Ddim;++k) acc = fmaf(a[k], W[(size_t)k*Ddim+n], acc);
    acc += bias[n];
    if(act) acc = fmaxf(acc,0.f);
    out[(size_t)b*Ddim+n]=acc;
}

__global__ __launch_bounds__(256)
void cond2(const float* __restrict__ hb,
           const float* __restrict__ W0, const float* __restrict__ b0, float* __restrict__ o0,
           const float* __restrict__ W1, const float* __restrict__ b1, float* __restrict__ o1){
    const float* W = blockIdx.z ? W1 : W0;
    const float* bi = blockIdx.z ? b1 : b0;
    float* o = blockIdx.z ? o1 : o0;
    const int n = blockIdx.x*256+threadIdx.x, b = blockIdx.y;
    const float* a = hb+(size_t)b*Ddim;
    float acc=0.f;
    for(int k=0;k<Ddim;++k) acc = fmaf(a[k], W[(size_t)k*Ddim+n], acc);
    o[(size_t)b*Ddim+n] = acc + bi[n];
}

__global__ __launch_bounds__(256)
void qa_kernel(const __half* __restrict__ q, const float* __restrict__ w,
               const float* __restrict__ bias, float* __restrict__ attn){
    const int warp=threadIdx.x>>5, lane=threadIdx.x&31;
    const int gi=blockIdx.x*8+warp, hh=gi&15, bn=gi>>4;
    const __half* qr = q+(size_t)bn*Ddim;
    float acc=0.f;
    #pragma unroll 4
    for(int k=lane;k<Ddim;k+=32) acc = fmaf(__half2float(qr[k]), w[k*Hdim+hh], acc);
    #pragma unroll
    for(int o=16;o;o>>=1) acc += __shfl_xor_sync(~0u,acc,o);
    if(lane==0){
        const int b=bn>>10, n=bn&1023;
        attn[(size_t)b*Hdim*Ndim + hh*Ndim + n] = (acc+bias[hh])*ISD;
    }
}

__global__ __launch_bounds__(256)
void softmax_kernel(float* __restrict__ attn, float* __restrict__ oa){
    __shared__ float sm[8];
    const int row=blockIdx.x;
    float4 v = reinterpret_cast<float4*>(attn+(size_t)row*Ndim)[threadIdx.x];
    float m = bmax(fmaxf(fmaxf(v.x,v.y),fmaxf(v.z,v.w)), sm);
    v.x=__expf(v.x-m); v.y=__expf(v.y-m); v.z=__expf(v.z-m); v.w=__expf(v.w-m);
    float s = bsum(v.x+v.y+v.z+v.w, sm);
    const float inv=1.f/s;
    v.x*=inv; v.y*=inv; v.z*=inv; v.w*=inv;
    reinterpret_cast<float4*>(attn+(size_t)row*Ndim)[threadIdx.x]=v;
    reinterpret_cast<float4*>(oa+(size_t)row*Ndim)[threadIdx.x]=v;
}

__global__ __launch_bounds__(256)
void globalq_kernel(const float* __restrict__ attn, const __half* __restrict__ q,
                    float* __restrict__ gq){
    __shared__ float part[256];
    const int bh=blockIdx.x, b=bh>>4, hh=bh&15;
    const int g=threadIdx.x>>6, d=threadIdx.x&63;
    const float* ar = attn+(size_t)bh*Ndim;
    float acc=0.f;
    for(int n=g;n<Ndim;n+=4)
        acc = fmaf(ar[n], __half2float(q[((size_t)(b*Ndim+n))*Ddim + hh*DEPTH + d]), acc);
    part[threadIdx.x]=acc;
    __syncthreads();
    if(g==0) gq[(size_t)bh*DEPTH+d] = part[d]+part[64+d]+part[128+d]+part[192+d];
}

__global__ __launch_bounds__(256)
void r_kernel(const float* __restrict__ gq, const __half* __restrict__ k,
              __half* __restrict__ v){
    const size_t i = (size_t)blockIdx.x*256+threadIdx.x;
    const int d=(int)(i&1023), b=(int)(i>>20);
    v[i] = __float2half_rn(gq[b*Ddim+d]*__half2float(k[i])*__half2float(v[i]));
}

#define SYMF(p,s) float* p; cudaGetSymbolAddress((void**)&p, s);
#define SYMH(p,s) __half* p; cudaGetSymbolAddress((void**)&p, s);

extern "C" void kernel_launch(void* const* d_in, const int* in_sizes, int n_in,
                              void* d_out, int out_size){
    const float* inputs=(const float*)d_in[0];
    const float* z=(const float*)d_in[1];
    const float *n1_hw=(const float*)d_in[2], *n1_hb=(const float*)d_in[3];
    const float *n1_gw=(const float*)d_in[4], *n1_gb=(const float*)d_in[5];
    const float *n1_bw=(const float*)d_in[6], *n1_bb=(const float*)d_in[7];
    const float *wq_w=(const float*)d_in[8],  *wq_b=(const float*)d_in[9];
    const float *wk_w=(const float*)d_in[10], *wk_b=(const float*)d_in[11];
    const float *wv_w=(const float*)d_in[12], *wv_b=(const float*)d_in[13];
    const float *qa_w=(const float*)d_in[14], *qa_b=(const float*)d_in[15];
    const float *out_w=(const float*)d_in[16],*out_b=(const float*)d_in[17];
    const float *n2_hw=(const float*)d_in[18],*n2_hb=(const float*)d_in[19];
    const float *n2_gw=(const float*)d_in[20],*n2_gb=(const float*)d_in[21];
    const float *n2_bw=(const float*)d_in[22],*n2_bb=(const float*)d_in[23];
    const float *mw1=(const float*)d_in[24],  *mb1=(const float*)d_in[25];
    const float *mw2=(const float*)d_in[26],  *mb2=(const float*)d_in[27];

    float* out=(float*)d_out;
    float* out_attn = out + (size_t)ROWS*Ddim;

    SYMF(ao,g_ao) SYMF(attn,g_attn) SYMF(gq,g_gq) SYMF(hbuf,g_h) SYMF(hbuf2,g_h2)
    SYMF(sc,g_scale) SYMF(sh,g_shift) SYMF(sc2,g_scale2) SYMF(sh2,g_shift2)
    SYMF(qkvb,g_qkvb)
    SYMH(xnh,g_xnh) SYMH(qh,g_qh) SYMH(kh,g_kh) SYMH(vh,g_vh) SYMH(mlph,g_mlph)
    SYMH(wqkv,g_wqkv) SYMH(woh,g_woh) SYMH(w1h,g_w1h) SYMH(w2h,g_w2h)

    cudaFuncSetAttribute(hgemm<1>, cudaFuncAttributeMaxDynamicSharedMemorySize, PIPESM);
    cudaFuncSetAttribute(hgemm<2>, cudaFuncAttributeMaxDynamicSharedMemorySize, PIPESM);
    cudaFuncSetAttribute(hgemm<3>, cudaFuncAttributeMaxDynamicSharedMemorySize, PIPESM);

    // fork streams (created fresh each call; kernel_launch runs only a handful of times)
    cudaStream_t sB, sC;
    cudaStreamCreateWithFlags(&sB, cudaStreamNonBlocking);
    cudaStreamCreateWithFlags(&sC, cudaStreamNonBlocking);
    cudaEvent_t eFork, eB, eC;
    cudaEventCreateWithFlags(&eFork, cudaEventDisableTiming);
    cudaEventCreateWithFlags(&eB, cudaEventDisableTiming);
    cudaEventCreateWithFlags(&eC, cudaEventDisableTiming);

    cudaEventRecord(eFork, 0);
    cudaStreamWaitEvent(sB, eFork, 0);
    cudaStreamWaitEvent(sC, eFork, 0);

    // stream B: weight preprocessing
    trh<<<dim3(32,32),256,0,sB>>>(wq_w, wqkv, Ddim, Ddim);
    trh<<<dim3(32,32),256,0,sB>>>(wk_w, wqkv + (size_t)Ddim*Ddim, Ddim, Ddim);
    trh<<<dim3(32,32),256,0,sB>>>(wv_w, wqkv + (size_t)2*Ddim*Ddim, Ddim, Ddim);
    trh<<<dim3(32,32),256,0,sB>>>(out_w, woh, Ddim, Ddim);
    trh<<<dim3(128,32),256,0,sB>>>(mw1, w1h, Ddim, MLPdim);
    trh<<<dim3(32,128),256,0,sB>>>(mw2, w2h, MLPdim, Ddim);
    concat3<<<12,256,0,sB>>>(wq_b, wk_b, wv_b, qkvb);
    cudaEventRecord(eB, sB);

    // stream C: norm2 conditioning (independent of everything but z)
    small_gemm<<<dim3(4,Bdim),256,0,sC>>>(z, n2_hw, n2_hb, hbuf2, 1);
    cond2<<<dim3(4,Bdim,2),256,0,sC>>>(hbuf2, n2_gw, n2_gb, sc2, n2_bw, n2_bb, sh2);
    cudaEventRecord(eC, sC);

    // main: norm1 conditioning + ln1
    small_gemm<<<dim3(4,Bdim),256>>>(z, n1_hw, n1_hb, hbuf, 1);
    cond2<<<dim3(4,Bdim,2),256>>>(hbuf, n1_gw, n1_gb, sc, n1_bw, n1_bb, sh);
    ln_mod<<<ROWS,256>>>(inputs, sc, sh, xnh);

    cudaStreamWaitEvent(0, eB, 0);
    // fused QKV
    hgemm<3><<<dim3(12,64),256,PIPESM>>>(xnh, wqkv, qkvb, nullptr, qh, kh, vh, Ddim, Ddim);

    qa_kernel<<<ROWS*Hdim/8,256>>>(qh, qa_w, qa_b, attn);
    softmax_kernel<<<Bdim*Hdim,256>>>(attn, out_attn);
    globalq_kernel<<<Bdim*Hdim,256>>>(attn, qh, gq);
    r_kernel<<<(size_t)ROWS*Ddim/256,256>>>(gq, kh, vh);

    hgemm<1><<<dim3(4,64),256,PIPESM>>>(vh, woh, out_b, inputs, ao, nullptr, nullptr, Ddim, Ddim);

    cudaStreamWaitEvent(0, eC, 0);
    ln_mod<<<ROWS,256>>>(ao, sc2, sh2, xnh);

    hgemm<2><<<dim3(16,64),256,PIPESM>>>(xnh, w1h, mb1, nullptr, mlph, nullptr, nullptr, MLPdim, Ddim);
    hgemm<1><<<dim3(4,64),256,PIPESM>>>(mlph, w2h, mb2, ao, out, nullptr, nullptr, Ddim, MLPdim);

    cudaEventDestroy(eFork);
    cudaEventDestroy(eB);
    cudaEventDestroy(eC);
    cudaStreamDestroy(sB);
    cudaStreamDestroy(sC);
}

// round 14
// speedup vs baseline: 1.3766x; 1.0209x over previous
#include <cuda_runtime.h>
#include <cuda_fp16.h>
#include <math.h>
#include <stdint.h>

#define Bdim 8
#define Ndim 1024
#define Ddim 1024
#define Hdim 16
#define DEPTH 64
#define MLPdim 4096
#define ROWS 8192
#define EPSLN 1e-6f
#define ISD 0.125f

__device__ float g_ao[ROWS*Ddim];
__device__ float g_attn[Bdim*Hdim*Ndim];
__device__ float g_gq[Bdim*Hdim*DEPTH];
__device__ float g_h[Bdim*Ddim];
__device__ float g_h2[Bdim*Ddim];
__device__ float g_scale[Bdim*Ddim];
__device__ float g_shift[Bdim*Ddim];
__device__ float g_scale2[Bdim*Ddim];
__device__ float g_shift2[Bdim*Ddim];
__device__ float g_qkvb[3*Ddim];
__device__ __half g_xnh[ROWS*Ddim];
__device__ __half g_qh[ROWS*Ddim];
__device__ __half g_kh[ROWS*Ddim];
__device__ __half g_vh[ROWS*Ddim];
__device__ __half g_mlph[(size_t)ROWS*MLPdim];
__device__ __half g_wqkv[(size_t)3*Ddim*Ddim];
__device__ __half g_woh[Ddim*Ddim];
__device__ __half g_w1h[(size_t)Ddim*MLPdim];
__device__ __half g_w2h[(size_t)Ddim*MLPdim];

__device__ __forceinline__ uint32_t cvsm(const void* p){
    uint32_t a; asm("{ .reg .u64 t; cvta.to.shared.u64 t, %1; cvt.u32.u64 %0, t; }":"=r"(a):"l"(p)); return a;
}
__device__ __forceinline__ void cp16(uint32_t d, const void* s){
    asm volatile("cp.async.cg.shared.global [%0], [%1], 16;" :: "r"(d), "l"(s));
}
__device__ __forceinline__ void ldsm4(uint32_t* r, uint32_t a){
    asm volatile("ldmatrix.sync.aligned.m8n8.x4.shared.b16 {%0,%1,%2,%3},[%4];"
        : "=r"(r[0]),"=r"(r[1]),"=r"(r[2]),"=r"(r[3]) : "r"(a));
}
__device__ __forceinline__ void mma_f16(float* d, const uint32_t* a, const uint32_t* b){
    asm volatile(
        "mma.sync.aligned.m16n8k16.row.col.f32.f16.f16.f32 "
        "{%0,%1,%2,%3},{%4,%5,%6,%7},{%8,%9},{%0,%1,%2,%3};"
        : "+f"(d[0]), "+f"(d[1]), "+f"(d[2]), "+f"(d[3])
        : "r"(a[0]), "r"(a[1]), "r"(a[2]), "r"(a[3]), "r"(b[0]), "r"(b[1]));
}

// ---------------- fp16 mma GEMM: CTA 128x256, warp 64x64, 4-stage ----------------
// EPI: 0 half(+b); 1 f32 +b+res; 2 half gelu(+b); 3 dual-output split by nBase>>10
#define ROWB 80
#define AB 10240
#define SLOTB 30720
#define NSTAGE 4
#define PIPESM (NSTAGE*SLOTB)

__device__ __forceinline__ void load_stage(uint32_t smb, const __half* A, const __half* Wt,
    int mBase, int nBase, int Ktot, int kB, int slot, int tid){
    uint32_t st = smb + slot*SLOTB;
    #pragma unroll
    for(int i=0;i<2;++i){
        int idx=i*256+tid, row=idx>>2, cc=idx&3;
        cp16(st + row*ROWB + cc*16, A + (size_t)(mBase+row)*Ktot + kB + cc*8);
    }
    #pragma unroll
    for(int i=0;i<4;++i){
        int idx=i*256+tid, row=idx>>2, cc=idx&3;
        cp16(st + AB + row*ROWB + cc*16, Wt + (size_t)(nBase+row)*Ktot + kB + cc*8);
    }
}

template<int EPI>
__global__ __launch_bounds__(256,1)
void hgemm(const __half* __restrict__ A, const __half* __restrict__ Wt,
           const float* __restrict__ bias, const float* __restrict__ res,
           void* __restrict__ Cv, void* __restrict__ C1, void* __restrict__ C2,
           int Ntot, int Ktot){
    extern __shared__ char smraw[];
    const uint32_t smb = cvsm(smraw);
    const int tid = threadIdx.x, lane = tid&31, warp = tid>>5;
    const int wm = warp>>2, wn = warp&3, g = lane>>2, c = lane&3;
    const int mBase = blockIdx.y*128, nBase = blockIdx.x*256;
    const int KS = Ktot/32;

    const uint32_t aoff = (uint32_t)(wm*64 + (lane&15))*ROWB + (uint32_t)(lane>>4)*16;
    const uint32_t boff = AB + (uint32_t)(wn*64 + (lane&7) + ((lane>>4)&1)*8)*ROWB
                          + (uint32_t)((lane>>3)&1)*16;

    float acc[4][8][4];
    #pragma unroll
    for(int i=0;i<4;++i)
        #pragma unroll
        for(int j=0;j<8;++j)
            #pragma unroll
            for(int q=0;q<4;++q) acc[i][j][q]=0.f;

    #pragma unroll
    for(int s=0;s<NSTAGE-1;++s){
        load_stage(smb, A, Wt, mBase, nBase, Ktot, s*32, s, tid);
        asm volatile("cp.async.commit_group;");
    }

    int slot = 0;
    for(int s=0;s<KS;++s){
        asm volatile("cp.async.wait_group %0;" :: "n"(NSTAGE-2));
        __syncthreads();
        const uint32_t sa = smb + (uint32_t)slot*SLOTB;

        uint32_t af[4][4], bf[8][2], bt[4];
        #pragma unroll
        for(int i=0;i<4;++i) ldsm4(af[i], sa + aoff + i*16*ROWB);
        #pragma unroll
        for(int jj=0;jj<4;++jj){
            ldsm4(bt, sa + boff + jj*16*ROWB);
            bf[2*jj][0]=bt[0]; bf[2*jj][1]=bt[1]; bf[2*jj+1][0]=bt[2]; bf[2*jj+1][1]=bt[3];
        }
        if(s+NSTAGE-1<KS){
            int ld = slot+NSTAGE-1; if(ld>=NSTAGE) ld-=NSTAGE;
            load_stage(smb, A, Wt, mBase, nBase, Ktot, (s+NSTAGE-1)*32, ld, tid);
        }
        asm volatile("cp.async.commit_group;");
        #pragma unroll
        for(int i=0;i<4;++i)
            #pragma unroll
            for(int j=0;j<8;++j)
                mma_f16(acc[i][j], af[i], bf[j]);

        #pragma unroll
        for(int i=0;i<4;++i) ldsm4(af[i], sa + aoff + i*16*ROWB + 32);
        #pragma unroll
        for(int jj=0;jj<4;++jj){
            ldsm4(bt, sa + boff + jj*16*ROWB + 32);
            bf[2*jj][0]=bt[0]; bf[2*jj][1]=bt[1]; bf[2*jj+1][0]=bt[2]; bf[2*jj+1][1]=bt[3];
        }
        #pragma unroll
        for(int i=0;i<4;++i)
            #pragma unroll
            for(int j=0;j<8;++j)
                mma_f16(acc[i][j], af[i], bf[j]);

        if(++slot==NSTAGE) slot=0;
    }

    __half* Cq = (__half*)Cv;
    if(EPI==3){
        const int sel = nBase>>10;
        Cq = sel==0 ? (__half*)Cv : (sel==1 ? (__half*)C1 : (__half*)C2);
    }

    #pragma unroll
    for(int i=0;i<4;++i){
        const int row0 = mBase + wm*64 + i*16 + g;
        #pragma unroll
        for(int j=0;j<8;++j){
            const int colg = nBase + wn*64 + j*8 + 2*c;
            const float b0 = bias[colg], b1 = bias[colg+1];
            #pragma unroll
            for(int half=0;half<2;++half){
                const int row = row0 + half*8;
                float v0 = acc[i][j][half*2+0] + b0;
                float v1 = acc[i][j][half*2+1] + b1;
                if(EPI==1){
                    const size_t off = (size_t)row*Ntot + colg;
                    float* Cf = (float*)Cv;
                    const float2 rr = *reinterpret_cast<const float2*>(res + off);
                    float2 o; o.x = v0+rr.x; o.y = v1+rr.y;
                    *reinterpret_cast<float2*>(Cf + off) = o;
                } else if(EPI==3){
                    const size_t off = (size_t)row*Ddim + (colg&1023);
                    *(__half2*)(Cq + off) = __floats2half2_rn(v0, v1);
                } else {
                    if(EPI==2){
                        v0 = 0.5f*v0*(1.f+erff(v0*0.7071067811865475f));
                        v1 = 0.5f*v1*(1.f+erff(v1*0.7071067811865475f));
                    }
                    const size_t off = (size_t)row*Ntot + colg;
                    *(__half2*)((__half*)Cv + off) = __floats2half2_rn(v0, v1);
                }
            }
        }
    }
}

__global__ __launch_bounds__(256)
void trh(const float* __restrict__ in, __half* __restrict__ out, int K, int N){
    __shared__ float t[32][33];
    const int n0 = blockIdx.x*32, k0 = blockIdx.y*32;
    const int tx = threadIdx.x & 31, ty = threadIdx.x >> 5;
    #pragma unroll
    for(int i=0;i<32;i+=8)
        t[ty+i][tx] = in[(size_t)(k0+ty+i)*N + n0+tx];
    __syncthreads();
    #pragma unroll
    for(int i=0;i<32;i+=8)
        out[(size_t)(n0+ty+i)*K + k0+tx] = __float2half_rn(t[tx][ty+i]);
}

__global__ void concat3(const float* __restrict__ a, const float* __restrict__ b,
                        const float* __restrict__ c, float* __restrict__ o){
    const int i = blockIdx.x*256+threadIdx.x;
    o[i] = (i<1024) ? a[i] : ((i<2048) ? b[i-1024] : c[i-2048]);
}

__device__ __forceinline__ float bsum(float v, float* sm){
    #pragma unroll
    for(int o=16;o;o>>=1) v += __shfl_xor_sync(~0u,v,o);
    int wd=threadIdx.x>>5;
    if((threadIdx.x&31)==0) sm[wd]=v;
    __syncthreads();
    float r=0.f;
    if(threadIdx.x<8){ r=sm[threadIdx.x];
        #pragma unroll
        for(int o=4;o;o>>=1) r += __shfl_xor_sync(0xFFu,r,o);
        if(threadIdx.x==0) sm[0]=r; }
    __syncthreads(); r=sm[0]; __syncthreads(); return r;
}
__device__ __forceinline__ float bmax(float v, float* sm){
    #pragma unroll
    for(int o=16;o;o>>=1) v = fmaxf(v,__shfl_xor_sync(~0u,v,o));
    int wd=threadIdx.x>>5;
    if((threadIdx.x&31)==0) sm[wd]=v;
    __syncthreads();
    float r=-1e30f;
    if(threadIdx.x<8){ r=sm[threadIdx.x];
        #pragma unroll
        for(int o=4;o;o>>=1) r = fmaxf(r,__shfl_xor_sync(0xFFu,r,o));
        if(threadIdx.x==0) sm[0]=r; }
    __syncthreads(); r=sm[0]; __syncthreads(); return r;
}

__global__ __launch_bounds__(256)
void ln_mod(const float* __restrict__ x, const float* __restrict__ sc,
            const float* __restrict__ sh, __half* __restrict__ out){
    __shared__ float sm[8];
    const int row=blockIdx.x, b=row>>10, n=row&1023;
    float4 v = reinterpret_cast<const float4*>(x+(size_t)row*Ddim)[threadIdx.x];
    float mean = bsum(v.x+v.y+v.z+v.w, sm)*(1.f/Ddim);
    float dx=v.x-mean, dy=v.y-mean, dz=v.z-mean, dw=v.w-mean;
    float var = bsum(dx*dx+dy*dy+dz*dz+dw*dw, sm)*(1.f/Ddim);
    float rs = rsqrtf(var+EPSLN);
    float s = sc[b*Ddim+n]*rs, t = sh[b*Ddim+n];
    __half2* o = reinterpret_cast<__half2*>(out+(size_t)row*Ddim) + threadIdx.x*2;
    o[0] = __floats2half2_rn(dx*s+t, dy*s+t);
    o[1] = __floats2half2_rn(dz*s+t, dw*s+t);
}

__global__ __launch_bounds__(256)
void small_gemm(const float* __restrict__ A, const float* __restrict__ W,
                const float* __restrict__ bias, float* __restrict__ out, int act){
    const int n = blockIdx.x*256+threadIdx.x, b = blockIdx.y;
    const float* a = A+(size_t)b*Ddim;
    float acc=0.f;
    for(int k=0;k<Ddim;++k) acc = fmaf(a[k], W[(size_t)k*Ddim+n], acc);
    acc += bias[n];
    if(act) acc = fmaxf(acc,0.f);
    out[(size_t)b*Ddim+n]=acc;
}

__global__ __launch_bounds__(256)
void cond2(const float* __restrict__ hb,
           const float* __restrict__ W0, const float* __restrict__ b0, float* __restrict__ o0,
           const float* __restrict__ W1, const float* __restrict__ b1, float* __restrict__ o1){
    const float* W = blockIdx.z ? W1 : W0;
    const float* bi = blockIdx.z ? b1 : b0;
    float* o = blockIdx.z ? o1 : o0;
    const int n = blockIdx.x*256+threadIdx.x, b = blockIdx.y;
    const float* a = hb+(size_t)b*Ddim;
    float acc=0.f;
    for(int k=0;k<Ddim;++k) acc = fmaf(a[k], W[(size_t)k*Ddim+n], acc);
    o[(size_t)b*Ddim+n] = acc + bi[n];
}

__global__ __launch_bounds__(256)
void qa_kernel(const __half* __restrict__ q, const float* __restrict__ w,
               const float* __restrict__ bias, float* __restrict__ attn){
    const int warp=threadIdx.x>>5, lane=threadIdx.x&31;
    const int gi=blockIdx.x*8+warp, hh=gi&15, bn=gi>>4;
    const __half* qr = q+(size_t)bn*Ddim;
    float acc=0.f;
    #pragma unroll 4
    for(int k=lane;k<Ddim;k+=32) acc = fmaf(__half2float(qr[k]), w[k*Hdim+hh], acc);
    #pragma unroll
    for(int o=16;o;o>>=1) acc += __shfl_xor_sync(~0u,acc,o);
    if(lane==0){
        const int b=bn>>10, n=bn&1023;
        attn[(size_t)b*Hdim*Ndim + hh*Ndim + n] = (acc+bias[hh])*ISD;
    }
}

__global__ __launch_bounds__(256)
void softmax_kernel(float* __restrict__ attn, float* __restrict__ oa){
    __shared__ float sm[8];
    const int row=blockIdx.x;
    float4 v = reinterpret_cast<float4*>(attn+(size_t)row*Ndim)[threadIdx.x];
    float m = bmax(fmaxf(fmaxf(v.x,v.y),fmaxf(v.z,v.w)), sm);
    v.x=__expf(v.x-m); v.y=__expf(v.y-m); v.z=__expf(v.z-m); v.w=__expf(v.w-m);
    float s = bsum(v.x+v.y+v.z+v.w, sm);
    const float inv=1.f/s;
    v.x*=inv; v.y*=inv; v.z*=inv; v.w*=inv;
    reinterpret_cast<float4*>(attn+(size_t)row*Ndim)[threadIdx.x]=v;
    reinterpret_cast<float4*>(oa+(size_t)row*Ndim)[threadIdx.x]=v;
}

__global__ __launch_bounds__(256)
void globalq_kernel(const float* __restrict__ attn, const __half* __restrict__ q,
                    float* __restrict__ gq){
    __shared__ float part[256];
    const int bh=blockIdx.x, b=bh>>4, hh=bh&15;
    const int g=threadIdx.x>>6, d=threadIdx.x&63;
    const float* ar = attn+(size_t)bh*Ndim;
    float acc=0.f;
    for(int n=g;n<Ndim;n+=4)
        acc = fmaf(ar[n], __half2float(q[((size_t)(b*Ndim+n))*Ddim + hh*DEPTH + d]), acc);
    part[threadIdx.x]=acc;
    __syncthreads();
    if(g==0) gq[(size_t)bh*DEPTH+d] = part[d]+part[64+d]+part[128+d]+part[192+d];
}

__global__ __launch_bounds__(256)
void r_kernel(const float* __restrict__ gq, const __half* __restrict__ k,
              __half* __restrict__ v){
    const size_t i = (size_t)blockIdx.x*256+threadIdx.x;
    const int d=(int)(i&1023), b=(int)(i>>20);
    v[i] = __float2half_rn(gq[b*Ddim+d]*__half2float(k[i])*__half2float(v[i]));
}

#define SYMF(p,s) float* p; cudaGetSymbolAddress((void**)&p, s);
#define SYMH(p,s) __half* p; cudaGetSymbolAddress((void**)&p, s);

extern "C" void kernel_launch(void* const* d_in, const int* in_sizes, int n_in,
                              void* d_out, int out_size){
    const float* inputs=(const float*)d_in[0];
    const float* z=(const float*)d_in[1];
    const float *n1_hw=(const float*)d_in[2], *n1_hb=(const float*)d_in[3];
    const float *n1_gw=(const float*)d_in[4], *n1_gb=(const float*)d_in[5];
    const float *n1_bw=(const float*)d_in[6], *n1_bb=(const float*)d_in[7];
    const float *wq_w=(const float*)d_in[8],  *wq_b=(const float*)d_in[9];
    const float *wk_w=(const float*)d_in[10], *wk_b=(const float*)d_in[11];
    const float *wv_w=(const float*)d_in[12], *wv_b=(const float*)d_in[13];
    const float *qa_w=(const float*)d_in[14], *qa_b=(const float*)d_in[15];
    const float *out_w=(const float*)d_in[16],*out_b=(const float*)d_in[17];
    const float *n2_hw=(const float*)d_in[18],*n2_hb=(const float*)d_in[19];
    const float *n2_gw=(const float*)d_in[20],*n2_gb=(const float*)d_in[21];
    const float *n2_bw=(const float*)d_in[22],*n2_bb=(const float*)d_in[23];
    const float *mw1=(const float*)d_in[24],  *mb1=(const float*)d_in[25];
    const float *mw2=(const float*)d_in[26],  *mb2=(const float*)d_in[27];

    float* out=(float*)d_out;
    float* out_attn = out + (size_t)ROWS*Ddim;

    SYMF(ao,g_ao) SYMF(attn,g_attn) SYMF(gq,g_gq) SYMF(hbuf,g_h) SYMF(hbuf2,g_h2)
    SYMF(sc,g_scale) SYMF(sh,g_shift) SYMF(sc2,g_scale2) SYMF(sh2,g_shift2)
    SYMF(qkvb,g_qkvb)
    SYMH(xnh,g_xnh) SYMH(qh,g_qh) SYMH(kh,g_kh) SYMH(vh,g_vh) SYMH(mlph,g_mlph)
    SYMH(wqkv,g_wqkv) SYMH(woh,g_woh) SYMH(w1h,g_w1h) SYMH(w2h,g_w2h)

    cudaFuncSetAttribute(hgemm<0>, cudaFuncAttributeMaxDynamicSharedMemorySize, PIPESM);
    cudaFuncSetAttribute(hgemm<1>, cudaFuncAttributeMaxDynamicSharedMemorySize, PIPESM);
    cudaFuncSetAttribute(hgemm<2>, cudaFuncAttributeMaxDynamicSharedMemorySize, PIPESM);
    cudaFuncSetAttribute(hgemm<3>, cudaFuncAttributeMaxDynamicSharedMemorySize, PIPESM);

    cudaStream_t sB, sC, sD;
    cudaStreamCreateWithFlags(&sB, cudaStreamNonBlocking);
    cudaStreamCreateWithFlags(&sC, cudaStreamNonBlocking);
    cudaStreamCreateWithFlags(&sD, cudaStreamNonBlocking);
    cudaEvent_t eFork, eB, eC, eLN1, eKV;
    cudaEventCreateWithFlags(&eFork, cudaEventDisableTiming);
    cudaEventCreateWithFlags(&eB, cudaEventDisableTiming);
    cudaEventCreateWithFlags(&eC, cudaEventDisableTiming);
    cudaEventCreateWithFlags(&eLN1, cudaEventDisableTiming);
    cudaEventCreateWithFlags(&eKV, cudaEventDisableTiming);

    cudaEventRecord(eFork, 0);
    cudaStreamWaitEvent(sB, eFork, 0);
    cudaStreamWaitEvent(sC, eFork, 0);

    // stream B: weight preprocessing
    trh<<<dim3(32,32),256,0,sB>>>(wq_w, wqkv, Ddim, Ddim);
    trh<<<dim3(32,32),256,0,sB>>>(wk_w, wqkv + (size_t)Ddim*Ddim, Ddim, Ddim);
    trh<<<dim3(32,32),256,0,sB>>>(wv_w, wqkv + (size_t)2*Ddim*Ddim, Ddim, Ddim);
    trh<<<dim3(32,32),256,0,sB>>>(out_w, woh, Ddim, Ddim);
    trh<<<dim3(128,32),256,0,sB>>>(mw1, w1h, Ddim, MLPdim);
    trh<<<dim3(32,128),256,0,sB>>>(mw2, w2h, MLPdim, Ddim);
    concat3<<<12,256,0,sB>>>(wq_b, wk_b, wv_b, qkvb);
    cudaEventRecord(eB, sB);

    // stream C: norm2 conditioning
    small_gemm<<<dim3(4,Bdim),256,0,sC>>>(z, n2_hw, n2_hb, hbuf2, 1);
    cond2<<<dim3(4,Bdim,2),256,0,sC>>>(hbuf2, n2_gw, n2_gb, sc2, n2_bw, n2_bb, sh2);
    cudaEventRecord(eC, sC);

    // main: norm1 conditioning + ln1
    small_gemm<<<dim3(4,Bdim),256>>>(z, n1_hw, n1_hb, hbuf, 1);
    cond2<<<dim3(4,Bdim,2),256>>>(hbuf, n1_gw, n1_gb, sc, n1_bw, n1_bb, sh);
    ln_mod<<<ROWS,256>>>(inputs, sc, sh, xnh);
    cudaEventRecord(eLN1, 0);
    cudaStreamWaitEvent(0, eB, 0);

    // stream D: kv GEMM (dual output) concurrent with q GEMM + qa chain on main
    cudaStreamWaitEvent(sD, eLN1, 0);
    cudaStreamWaitEvent(sD, eB, 0);
    hgemm<3><<<dim3(8,64),256,PIPESM,sD>>>(xnh, wqkv + (size_t)Ddim*Ddim, qkvb + Ddim,
                                           nullptr, kh, vh, nullptr, 2048, Ddim);
    cudaEventRecord(eKV, sD);

    // main: q GEMM then attention chain (needs only q)
    hgemm<0><<<dim3(4,64),256,PIPESM>>>(xnh, wqkv, qkvb, nullptr, qh, nullptr, nullptr, Ddim, Ddim);
    qa_kernel<<<ROWS*Hdim/8,256>>>(qh, qa_w, qa_b, attn);
    softmax_kernel<<<Bdim*Hdim,256>>>(attn, out_attn);
    globalq_kernel<<<Bdim*Hdim,256>>>(attn, qh, gq);

    cudaStreamWaitEvent(0, eKV, 0);
    r_kernel<<<(size_t)ROWS*Ddim/256,256>>>(gq, kh, vh);

    hgemm<1><<<dim3(4,64),256,PIPESM>>>(vh, woh, out_b, inputs, ao, nullptr, nullptr, Ddim, Ddim);

    cudaStreamWaitEvent(0, eC, 0);
    ln_mod<<<ROWS,256>>>(ao, sc2, sh2, xnh);

    hgemm<2><<<dim3(16,64),256,PIPESM>>>(xnh, w1h, mb1, nullptr, mlph, nullptr, nullptr, MLPdim, Ddim);
    hgemm<1><<<dim3(4,64),256,PIPESM>>>(mlph, w2h, mb2, ao, out, nullptr, nullptr, Ddim, MLPdim);

    cudaEventDestroy(eFork); cudaEventDestroy(eB); cudaEventDestroy(eC);
    cudaEventDestroy(eLN1); cudaEventDestroy(eKV);
    cudaStreamDestroy(sB); cudaStreamDestroy(sC); cudaStreamDestroy(sD);
}

// round 15
// speedup vs baseline: 1.3963x; 1.0143x over previous
#include <cuda_runtime.h>
#include <cuda_fp16.h>
#include <math.h>
#include <stdint.h>

#define Bdim 8
#define Ndim 1024
#define Ddim 1024
#define Hdim 16
#define DEPTH 64
#define MLPdim 4096
#define ROWS 8192
#define EPSLN 1e-6f
#define ISD 0.125f

__device__ float g_ao[ROWS*Ddim];
__device__ float g_attn[Bdim*Hdim*Ndim];
__device__ float g_gq[Bdim*Hdim*DEPTH];
__device__ float g_h[Bdim*Ddim];
__device__ float g_h2[Bdim*Ddim];
__device__ float g_scale[Bdim*Ddim];
__device__ float g_shift[Bdim*Ddim];
__device__ float g_scale2[Bdim*Ddim];
__device__ float g_shift2[Bdim*Ddim];
__device__ float g_qkvb[3*Ddim];
__device__ __half g_xnh[ROWS*Ddim];
__device__ __half g_qh[ROWS*Ddim];
__device__ __half g_kh[ROWS*Ddim];
__device__ __half g_vh[ROWS*Ddim];
__device__ __half g_mlph[(size_t)ROWS*MLPdim];
__device__ __half g_wqkv[(size_t)3*Ddim*Ddim];
__device__ __half g_woh[Ddim*Ddim];
__device__ __half g_w1h[(size_t)Ddim*MLPdim];
__device__ __half g_w2h[(size_t)Ddim*MLPdim];

__device__ __forceinline__ uint32_t cvsm(const void* p){
    uint32_t a; asm("{ .reg .u64 t; cvta.to.shared.u64 t, %1; cvt.u32.u64 %0, t; }":"=r"(a):"l"(p)); return a;
}
__device__ __forceinline__ void cp16(uint32_t d, const void* s){
    asm volatile("cp.async.cg.shared.global [%0], [%1], 16;" :: "r"(d), "l"(s));
}
__device__ __forceinline__ void ldsm4(uint32_t* r, uint32_t a){
    asm volatile("ldmatrix.sync.aligned.m8n8.x4.shared.b16 {%0,%1,%2,%3},[%4];"
        : "=r"(r[0]),"=r"(r[1]),"=r"(r[2]),"=r"(r[3]) : "r"(a));
}
__device__ __forceinline__ void mma_f16(float* d, const uint32_t* a, const uint32_t* b){
    asm volatile(
        "mma.sync.aligned.m16n8k16.row.col.f32.f16.f16.f32 "
        "{%0,%1,%2,%3},{%4,%5,%6,%7},{%8,%9},{%0,%1,%2,%3};"
        : "+f"(d[0]), "+f"(d[1]), "+f"(d[2]), "+f"(d[3])
        : "r"(a[0]), "r"(a[1]), "r"(a[2]), "r"(a[3]), "r"(b[0]), "r"(b[1]));
}

// ---------------- fp16 mma GEMM: CTA 128x256, warp 64x64, 4-stage ----------------
// EPI: 0 half(+b); 1 f32 +b+res; 2 half gelu(+b); 3 dual-output split by nBase>>10
#define ROWB 80
#define AB 10240
#define SLOTB 30720
#define NSTAGE 4
#define PIPESM (NSTAGE*SLOTB)

__device__ __forceinline__ void load_stage(uint32_t smb, const __half* A, const __half* Wt,
    int mBase, int nBase, int Ktot, int kB, int slot, int tid){
    uint32_t st = smb + slot*SLOTB;
    #pragma unroll
    for(int i=0;i<2;++i){
        int idx=i*256+tid, row=idx>>2, cc=idx&3;
        cp16(st + row*ROWB + cc*16, A + (size_t)(mBase+row)*Ktot + kB + cc*8);
    }
    #pragma unroll
    for(int i=0;i<4;++i){
        int idx=i*256+tid, row=idx>>2, cc=idx&3;
        cp16(st + AB + row*ROWB + cc*16, Wt + (size_t)(nBase+row)*Ktot + kB + cc*8);
    }
}

template<int EPI>
__global__ __launch_bounds__(256,1)
void hgemm(const __half* __restrict__ A, const __half* __restrict__ Wt,
           const float* __restrict__ bias, const float* __restrict__ res,
           void* __restrict__ Cv, void* __restrict__ C1, void* __restrict__ C2,
           int Ntot, int Ktot, int mOff){
    extern __shared__ char smraw[];
    const uint32_t smb = cvsm(smraw);
    const int tid = threadIdx.x, lane = tid&31, warp = tid>>5;
    const int wm = warp>>2, wn = warp&3, g = lane>>2, c = lane&3;
    const int mBase = mOff + blockIdx.y*128, nBase = blockIdx.x*256;
    const int KS = Ktot/32;

    const uint32_t aoff = (uint32_t)(wm*64 + (lane&15))*ROWB + (uint32_t)(lane>>4)*16;
    const uint32_t boff = AB + (uint32_t)(wn*64 + (lane&7) + ((lane>>4)&1)*8)*ROWB
                          + (uint32_t)((lane>>3)&1)*16;

    float acc[4][8][4];
    #pragma unroll
    for(int i=0;i<4;++i)
        #pragma unroll
        for(int j=0;j<8;++j)
            #pragma unroll
            for(int q=0;q<4;++q) acc[i][j][q]=0.f;

    #pragma unroll
    for(int s=0;s<NSTAGE-1;++s){
        load_stage(smb, A, Wt, mBase, nBase, Ktot, s*32, s, tid);
        asm volatile("cp.async.commit_group;");
    }

    int slot = 0;
    for(int s=0;s<KS;++s){
        asm volatile("cp.async.wait_group %0;" :: "n"(NSTAGE-2));
        __syncthreads();
        const uint32_t sa = smb + (uint32_t)slot*SLOTB;

        uint32_t af[4][4], bf[8][2], bt[4];
        #pragma unroll
        for(int i=0;i<4;++i) ldsm4(af[i], sa + aoff + i*16*ROWB);
        #pragma unroll
        for(int jj=0;jj<4;++jj){
            ldsm4(bt, sa + boff + jj*16*ROWB);
            bf[2*jj][0]=bt[0]; bf[2*jj][1]=bt[1]; bf[2*jj+1][0]=bt[2]; bf[2*jj+1][1]=bt[3];
        }
        if(s+NSTAGE-1<KS){
            int ld = slot+NSTAGE-1; if(ld>=NSTAGE) ld-=NSTAGE;
            load_stage(smb, A, Wt, mBase, nBase, Ktot, (s+NSTAGE-1)*32, ld, tid);
        }
        asm volatile("cp.async.commit_group;");
        #pragma unroll
        for(int i=0;i<4;++i)
            #pragma unroll
            for(int j=0;j<8;++j)
                mma_f16(acc[i][j], af[i], bf[j]);

        #pragma unroll
        for(int i=0;i<4;++i) ldsm4(af[i], sa + aoff + i*16*ROWB + 32);
        #pragma unroll
        for(int jj=0;jj<4;++jj){
            ldsm4(bt, sa + boff + jj*16*ROWB + 32);
            bf[2*jj][0]=bt[0]; bf[2*jj][1]=bt[1]; bf[2*jj+1][0]=bt[2]; bf[2*jj+1][1]=bt[3];
        }
        #pragma unroll
        for(int i=0;i<4;++i)
            #pragma unroll
            for(int j=0;j<8;++j)
                mma_f16(acc[i][j], af[i], bf[j]);

        if(++slot==NSTAGE) slot=0;
    }

    __half* Cq = (__half*)Cv;
    if(EPI==3){
        const int sel = nBase>>10;
        Cq = sel==0 ? (__half*)Cv : (sel==1 ? (__half*)C1 : (__half*)C2);
    }

    #pragma unroll
    for(int i=0;i<4;++i){
        const int row0 = mBase + wm*64 + i*16 + g;
        #pragma unroll
        for(int j=0;j<8;++j){
            const int colg = nBase + wn*64 + j*8 + 2*c;
            const float b0 = bias[colg], b1 = bias[colg+1];
            #pragma unroll
            for(int half=0;half<2;++half){
                const int row = row0 + half*8;
                float v0 = acc[i][j][half*2+0] + b0;
                float v1 = acc[i][j][half*2+1] + b1;
                if(EPI==1){
                    const size_t off = (size_t)row*Ntot + colg;
                    float* Cf = (float*)Cv;
                    const float2 rr = *reinterpret_cast<const float2*>(res + off);
                    float2 o; o.x = v0+rr.x; o.y = v1+rr.y;
                    *reinterpret_cast<float2*>(Cf + off) = o;
                } else if(EPI==3){
                    const size_t off = (size_t)row*Ddim + (colg&1023);
                    *(__half2*)(Cq + off) = __floats2half2_rn(v0, v1);
                } else {
                    if(EPI==2){
                        v0 = 0.5f*v0*(1.f+erff(v0*0.7071067811865475f));
                        v1 = 0.5f*v1*(1.f+erff(v1*0.7071067811865475f));
                    }
                    const size_t off = (size_t)row*Ntot + colg;
                    *(__half2*)((__half*)Cv + off) = __floats2half2_rn(v0, v1);
                }
            }
        }
    }
}

__global__ __launch_bounds__(256)
void trh(const float* __restrict__ in, __half* __restrict__ out, int K, int N){
    __shared__ float t[32][33];
    const int n0 = blockIdx.x*32, k0 = blockIdx.y*32;
    const int tx = threadIdx.x & 31, ty = threadIdx.x >> 5;
    #pragma unroll
    for(int i=0;i<32;i+=8)
        t[ty+i][tx] = in[(size_t)(k0+ty+i)*N + n0+tx];
    __syncthreads();
    #pragma unroll
    for(int i=0;i<32;i+=8)
        out[(size_t)(n0+ty+i)*K + k0+tx] = __float2half_rn(t[tx][ty+i]);
}

__global__ void concat3(const float* __restrict__ a, const float* __restrict__ b,
                        const float* __restrict__ c, float* __restrict__ o){
    const int i = blockIdx.x*256+threadIdx.x;
    o[i] = (i<1024) ? a[i] : ((i<2048) ? b[i-1024] : c[i-2048]);
}

__device__ __forceinline__ float bsum(float v, float* sm){
    #pragma unroll
    for(int o=16;o;o>>=1) v += __shfl_xor_sync(~0u,v,o);
    int wd=threadIdx.x>>5;
    if((threadIdx.x&31)==0) sm[wd]=v;
    __syncthreads();
    float r=0.f;
    if(threadIdx.x<8){ r=sm[threadIdx.x];
        #pragma unroll
        for(int o=4;o;o>>=1) r += __shfl_xor_sync(0xFFu,r,o);
        if(threadIdx.x==0) sm[0]=r; }
    __syncthreads(); r=sm[0]; __syncthreads(); return r;
}
__device__ __forceinline__ float bmax(float v, float* sm){
    #pragma unroll
    for(int o=16;o;o>>=1) v = fmaxf(v,__shfl_xor_sync(~0u,v,o));
    int wd=threadIdx.x>>5;
    if((threadIdx.x&31)==0) sm[wd]=v;
    __syncthreads();
    float r=-1e30f;
    if(threadIdx.x<8){ r=sm[threadIdx.x];
        #pragma unroll
        for(int o=4;o;o>>=1) r = fmaxf(r,__shfl_xor_sync(0xFFu,r,o));
        if(threadIdx.x==0) sm[0]=r; }
    __syncthreads(); r=sm[0]; __syncthreads(); return r;
}

// ln over rows [rOff, rOff+grid) — row = rOff + blockIdx.x
__global__ __launch_bounds__(256)
void ln_mod(const float* __restrict__ x, const float* __restrict__ sc,
            const float* __restrict__ sh, __half* __restrict__ out, int rOff){
    __shared__ float sm[8];
    const int row=rOff+blockIdx.x, b=row>>10, n=row&1023;
    float4 v = reinterpret_cast<const float4*>(x+(size_t)row*Ddim)[threadIdx.x];
    float mean = bsum(v.x+v.y+v.z+v.w, sm)*(1.f/Ddim);
    float dx=v.x-mean, dy=v.y-mean, dz=v.z-mean, dw=v.w-mean;
    float var = bsum(dx*dx+dy*dy+dz*dz+dw*dw, sm)*(1.f/Ddim);
    float rs = rsqrtf(var+EPSLN);
    float s = sc[b*Ddim+n]*rs, t = sh[b*Ddim+n];
    __half2* o = reinterpret_cast<__half2*>(out+(size_t)row*Ddim) + threadIdx.x*2;
    o[0] = __floats2half2_rn(dx*s+t, dy*s+t);
    o[1] = __floats2half2_rn(dz*s+t, dw*s+t);
}

__global__ __launch_bounds__(256)
void small_gemm(const float* __restrict__ A, const float* __restrict__ W,
                const float* __restrict__ bias, float* __restrict__ out, int act){
    const int n = blockIdx.x*256+threadIdx.x, b = blockIdx.y;
    const float* a = A+(size_t)b*Ddim;
    float acc=0.f;
    for(int k=0;k<Ddim;++k) acc = fmaf(a[k], W[(size_t)k*Ddim+n], acc);
    acc += bias[n];
    if(act) acc = fmaxf(acc,0.f);
    out[(size_t)b*Ddim+n]=acc;
}

__global__ __launch_bounds__(256)
void cond2(const float* __restrict__ hb,
           const float* __restrict__ W0, const float* __restrict__ b0, float* __restrict__ o0,
           const float* __restrict__ W1, const float* __restrict__ b1, float* __restrict__ o1){
    const float* W = blockIdx.z ? W1 : W0;
    const float* bi = blockIdx.z ? b1 : b0;
    float* o = blockIdx.z ? o1 : o0;
    const int n = blockIdx.x*256+threadIdx.x, b = blockIdx.y;
    const float* a = hb+(size_t)b*Ddim;
    float acc=0.f;
    for(int k=0;k<Ddim;++k) acc = fmaf(a[k], W[(size_t)k*Ddim+n], acc);
    o[(size_t)b*Ddim+n] = acc + bi[n];
}

__global__ __launch_bounds__(256)
void qa_kernel(const __half* __restrict__ q, const float* __restrict__ w,
               const float* __restrict__ bias, float* __restrict__ attn){
    const int warp=threadIdx.x>>5, lane=threadIdx.x&31;
    const int gi=blockIdx.x*8+warp, hh=gi&15, bn=gi>>4;
    const __half* qr = q+(size_t)bn*Ddim;
    float acc=0.f;
    #pragma unroll 4
    for(int k=lane;k<Ddim;k+=32) acc = fmaf(__half2float(qr[k]), w[k*Hdim+hh], acc);
    #pragma unroll
    for(int o=16;o;o>>=1) acc += __shfl_xor_sync(~0u,acc,o);
    if(lane==0){
        const int b=bn>>10, n=bn&1023;
        attn[(size_t)b*Hdim*Ndim + hh*Ndim + n] = (acc+bias[hh])*ISD;
    }
}

__global__ __launch_bounds__(256)
void softmax_kernel(float* __restrict__ attn, float* __restrict__ oa){
    __shared__ float sm[8];
    const int row=blockIdx.x;
    float4 v = reinterpret_cast<float4*>(attn+(size_t)row*Ndim)[threadIdx.x];
    float m = bmax(fmaxf(fmaxf(v.x,v.y),fmaxf(v.z,v.w)), sm);
    v.x=__expf(v.x-m); v.y=__expf(v.y-m); v.z=__expf(v.z-m); v.w=__expf(v.w-m);
    float s = bsum(v.x+v.y+v.z+v.w, sm);
    const float inv=1.f/s;
    v.x*=inv; v.y*=inv; v.z*=inv; v.w*=inv;
    reinterpret_cast<float4*>(attn+(size_t)row*Ndim)[threadIdx.x]=v;
    reinterpret_cast<float4*>(oa+(size_t)row*Ndim)[threadIdx.x]=v;
}

__global__ __launch_bounds__(256)
void globalq_kernel(const float* __restrict__ attn, const __half* __restrict__ q,
                    float* __restrict__ gq){
    __shared__ float part[256];
    const int bh=blockIdx.x, b=bh>>4, hh=bh&15;
    const int g=threadIdx.x>>6, d=threadIdx.x&63;
    const float* ar = attn+(size_t)bh*Ndim;
    float acc=0.f;
    for(int n=g;n<Ndim;n+=4)
        acc = fmaf(ar[n], __half2float(q[((size_t)(b*Ndim+n))*Ddim + hh*DEPTH + d]), acc);
    part[threadIdx.x]=acc;
    __syncthreads();
    if(g==0) gq[(size_t)bh*DEPTH+d] = part[d]+part[64+d]+part[128+d]+part[192+d];
}

__global__ __launch_bounds__(256)
void r_kernel(const float* __restrict__ gq, const __half* __restrict__ k,
              __half* __restrict__ v){
    const size_t i = (size_t)blockIdx.x*256+threadIdx.x;
    const int d=(int)(i&1023), b=(int)(i>>20);
    v[i] = __float2half_rn(gq[b*Ddim+d]*__half2float(k[i])*__half2float(v[i]));
}

#define SYMF(p,s) float* p; cudaGetSymbolAddress((void**)&p, s);
#define SYMH(p,s) __half* p; cudaGetSymbolAddress((void**)&p, s);

extern "C" void kernel_launch(void* const* d_in, const int* in_sizes, int n_in,
                              void* d_out, int out_size){
    const float* inputs=(const float*)d_in[0];
    const float* z=(const float*)d_in[1];
    const float *n1_hw=(const float*)d_in[2], *n1_hb=(const float*)d_in[3];
    const float *n1_gw=(const float*)d_in[4], *n1_gb=(const float*)d_in[5];
    const float *n1_bw=(const float*)d_in[6], *n1_bb=(const float*)d_in[7];
    const float *wq_w=(const float*)d_in[8],  *wq_b=(const float*)d_in[9];
    const float *wk_w=(const float*)d_in[10], *wk_b=(const float*)d_in[11];
    const float *wv_w=(const float*)d_in[12], *wv_b=(const float*)d_in[13];
    const float *qa_w=(const float*)d_in[14], *qa_b=(const float*)d_in[15];
    const float *out_w=(const float*)d_in[16],*out_b=(const float*)d_in[17];
    const float *n2_hw=(const float*)d_in[18],*n2_hb=(const float*)d_in[19];
    const float *n2_gw=(const float*)d_in[20],*n2_gb=(const float*)d_in[21];
    const float *n2_bw=(const float*)d_in[22],*n2_bb=(const float*)d_in[23];
    const float *mw1=(const float*)d_in[24],  *mb1=(const float*)d_in[25];
    const float *mw2=(const float*)d_in[26],  *mb2=(const float*)d_in[27];

    float* out=(float*)d_out;
    float* out_attn = out + (size_t)ROWS*Ddim;

    SYMF(ao,g_ao) SYMF(attn,g_attn) SYMF(gq,g_gq) SYMF(hbuf,g_h) SYMF(hbuf2,g_h2)
    SYMF(sc,g_scale) SYMF(sh,g_shift) SYMF(sc2,g_scale2) SYMF(sh2,g_shift2)
    SYMF(qkvb,g_qkvb)
    SYMH(xnh,g_xnh) SYMH(qh,g_qh) SYMH(kh,g_kh) SYMH(vh,g_vh) SYMH(mlph,g_mlph)
    SYMH(wqkv,g_wqkv) SYMH(woh,g_woh) SYMH(w1h,g_w1h) SYMH(w2h,g_w2h)

    cudaFuncSetAttribute(hgemm<0>, cudaFuncAttributeMaxDynamicSharedMemorySize, PIPESM);
    cudaFuncSetAttribute(hgemm<1>, cudaFuncAttributeMaxDynamicSharedMemorySize, PIPESM);
    cudaFuncSetAttribute(hgemm<2>, cudaFuncAttributeMaxDynamicSharedMemorySize, PIPESM);
    cudaFuncSetAttribute(hgemm<3>, cudaFuncAttributeMaxDynamicSharedMemorySize, PIPESM);

    cudaStream_t sB, sC, sD;
    cudaStreamCreateWithFlags(&sB, cudaStreamNonBlocking);
    cudaStreamCreateWithFlags(&sC, cudaStreamNonBlocking);
    cudaStreamCreateWithFlags(&sD, cudaStreamNonBlocking);
    cudaEvent_t eFork, eB, eC, eLN1, eKV, eR, eE;
    cudaEventCreateWithFlags(&eFork, cudaEventDisableTiming);
    cudaEventCreateWithFlags(&eB, cudaEventDisableTiming);
    cudaEventCreateWithFlags(&eC, cudaEventDisableTiming);
    cudaEventCreateWithFlags(&eLN1, cudaEventDisableTiming);
    cudaEventCreateWithFlags(&eKV, cudaEventDisableTiming);
    cudaEventCreateWithFlags(&eR, cudaEventDisableTiming);
    cudaEventCreateWithFlags(&eE, cudaEventDisableTiming);

    cudaEventRecord(eFork, 0);
    cudaStreamWaitEvent(sB, eFork, 0);
    cudaStreamWaitEvent(sC, eFork, 0);

    // stream B: weight preprocessing
    trh<<<dim3(32,32),256,0,sB>>>(wq_w, wqkv, Ddim, Ddim);
    trh<<<dim3(32,32),256,0,sB>>>(wk_w, wqkv + (size_t)Ddim*Ddim, Ddim, Ddim);
    trh<<<dim3(32,32),256,0,sB>>>(wv_w, wqkv + (size_t)2*Ddim*Ddim, Ddim, Ddim);
    trh<<<dim3(32,32),256,0,sB>>>(out_w, woh, Ddim, Ddim);
    trh<<<dim3(128,32),256,0,sB>>>(mw1, w1h, Ddim, MLPdim);
    trh<<<dim3(32,128),256,0,sB>>>(mw2, w2h, MLPdim, Ddim);
    concat3<<<12,256,0,sB>>>(wq_b, wk_b, wv_b, qkvb);
    cudaEventRecord(eB, sB);

    // stream C: norm2 conditioning
    small_gemm<<<dim3(4,Bdim),256,0,sC>>>(z, n2_hw, n2_hb, hbuf2, 1);
    cond2<<<dim3(4,Bdim,2),256,0,sC>>>(hbuf2, n2_gw, n2_gb, sc2, n2_bw, n2_bb, sh2);
    cudaEventRecord(eC, sC);

    // main: norm1 conditioning + ln1
    small_gemm<<<dim3(4,Bdim),256>>>(z, n1_hw, n1_hb, hbuf, 1);
    cond2<<<dim3(4,Bdim,2),256>>>(hbuf, n1_gw, n1_gb, sc, n1_bw, n1_bb, sh);
    ln_mod<<<ROWS,256>>>(inputs, sc, sh, xnh, 0);
    cudaEventRecord(eLN1, 0);
    cudaStreamWaitEvent(0, eB, 0);

    // stream D: kv GEMM concurrent with q GEMM + qa chain
    cudaStreamWaitEvent(sD, eLN1, 0);
    cudaStreamWaitEvent(sD, eB, 0);
    hgemm<3><<<dim3(8,64),256,PIPESM,sD>>>(xnh, wqkv + (size_t)Ddim*Ddim, qkvb + Ddim,
                                           nullptr, kh, vh, nullptr, 2048, Ddim, 0);
    cudaEventRecord(eKV, sD);

    hgemm<0><<<dim3(4,64),256,PIPESM>>>(xnh, wqkv, qkvb, nullptr, qh, nullptr, nullptr, Ddim, Ddim, 0);
    qa_kernel<<<ROWS*Hdim/8,256>>>(qh, qa_w, qa_b, attn);
    softmax_kernel<<<Bdim*Hdim,256>>>(attn, out_attn);
    globalq_kernel<<<Bdim*Hdim,256>>>(attn, qh, gq);

    cudaStreamWaitEvent(0, eKV, 0);
    r_kernel<<<(size_t)ROWS*Ddim/256,256>>>(gq, kh, vh);
    cudaEventRecord(eR, 0);

    // post-attention chain split by M-halves: main = rows [0,4096), sD = rows [4096,8192)
    cudaStreamWaitEvent(sD, eR, 0);
    cudaStreamWaitEvent(sD, eC, 0);
    cudaStreamWaitEvent(0, eC, 0);

    // half 0 (main)
    hgemm<1><<<dim3(4,32),256,PIPESM>>>(vh, woh, out_b, inputs, ao, nullptr, nullptr, Ddim, Ddim, 0);
    ln_mod<<<4096,256>>>(ao, sc2, sh2, xnh, 0);
    hgemm<2><<<dim3(16,32),256,PIPESM>>>(xnh, w1h, mb1, nullptr, mlph, nullptr, nullptr, MLPdim, Ddim, 0);
    hgemm<1><<<dim3(4,32),256,PIPESM>>>(mlph, w2h, mb2, ao, out, nullptr, nullptr, Ddim, MLPdim, 0);

    // half 1 (stream D)
    hgemm<1><<<dim3(4,32),256,PIPESM,sD>>>(vh, woh, out_b, inputs, ao, nullptr, nullptr, Ddim, Ddim, 4096);
    ln_mod<<<4096,256,0,sD>>>(ao, sc2, sh2, xnh, 4096);
    hgemm<2><<<dim3(16,32),256,PIPESM,sD>>>(xnh, w1h, mb1, nullptr, mlph, nullptr, nullptr, MLPdim, Ddim, 4096);
    hgemm<1><<<dim3(4,32),256,PIPESM,sD>>>(mlph, w2h, mb2, ao, out, nullptr, nullptr, Ddim, MLPdim, 4096);
    cudaEventRecord(eE, sD);
    cudaStreamWaitEvent(0, eE, 0);

    cudaEventDestroy(eFork); cudaEventDestroy(eB); cudaEventDestroy(eC);
    cudaEventDestroy(eLN1); cudaEventDestroy(eKV); cudaEventDestroy(eR); cudaEventDestroy(eE);
    cudaStreamDestroy(sB); cudaStreamDestroy(sC); cudaStreamDestroy(sD);
}